// round 7
// baseline (speedup 1.0000x reference)
#include <cuda_runtime.h>
#include <cuda_fp16.h>
#include <cstdint>

#define HW 192
#define F 100
#define CP 112            // padded channel count (stored)
#define PP 112            // conv_hidden smem pitch in halves (224B; 2-way LDSM conflict, acceptable)
#define PITCH 120         // kp_gemm smem pitch (conflict-free)
#define KK 441
#define KKP 448           // padded logit count

// Activation ping-pong buffers: fp16 NHWC[112]: 2*192*192*112 halves = 16.5 MB each.
__device__ __half g_act0[2 * HW * HW * CP];
__device__ __half g_act1[2 * HW * HW * CP];
// Transformed hidden weights: [layer7][tap25][co128][ci112] fp16 = 10 MB.
__device__ __half g_wt[7 * 25 * 128 * CP];
// Transformed kp weights: [448][112] fp16.
__device__ __half g_wkp[KKP * CP];
// Logits: [b][y][x][448] fp16 = 66 MB.
__device__ __half g_logits[2 * HW * HW * KKP];

// ---------------------------------------------------------------------------
// PTX helpers
// ---------------------------------------------------------------------------
__device__ __forceinline__ uint32_t smem_u32(const void* p) {
    return (uint32_t)__cvta_generic_to_shared(p);
}
__device__ __forceinline__ void ldm_x4(uint32_t* r, uint32_t addr) {
    asm volatile("ldmatrix.sync.aligned.m8n8.x4.shared.b16 {%0,%1,%2,%3}, [%4];"
                 : "=r"(r[0]), "=r"(r[1]), "=r"(r[2]), "=r"(r[3]) : "r"(addr));
}
__device__ __forceinline__ void mma16816(float* c, const uint32_t* a, const uint32_t* b) {
    asm volatile(
        "mma.sync.aligned.m16n8k16.row.col.f32.f16.f16.f32 "
        "{%0,%1,%2,%3}, {%4,%5,%6,%7}, {%8,%9}, {%0,%1,%2,%3};"
        : "+f"(c[0]), "+f"(c[1]), "+f"(c[2]), "+f"(c[3])
        : "r"(a[0]), "r"(a[1]), "r"(a[2]), "r"(a[3]), "r"(b[0]), "r"(b[1]));
}
__device__ __forceinline__ void cp16(uint32_t dst, const void* src) {
    asm volatile("cp.async.cg.shared.global [%0], [%1], 16;" :: "r"(dst), "l"(src));
}
__device__ __forceinline__ void cp16z(uint32_t dst, const void* src, int srcsz) {
    asm volatile("cp.async.cg.shared.global [%0], [%1], 16, %2;"
                 :: "r"(dst), "l"(src), "r"(srcsz));
}
__device__ __forceinline__ void cp_commit() {
    asm volatile("cp.async.commit_group;");
}
template <int N>
__device__ __forceinline__ void cp_wait() {
    asm volatile("cp.async.wait_group %0;" :: "n"(N));
}

// ---------------------------------------------------------------------------
// Weight transforms
// ---------------------------------------------------------------------------
__global__ void wt_transform(const float* __restrict__ w_hid) {
    int idx = blockIdx.x * 256 + threadIdx.x;
    if (idx >= 7 * 25 * 128 * CP) return;
    int ci = idx % CP;
    int co = (idx / CP) % 128;
    int tap = (idx / (CP * 128)) % 25;
    int l = idx / (CP * 128 * 25);
    float v = 0.f;
    if (co < F && ci < F)
        v = w_hid[(((size_t)l * F + co) * F + ci) * 25 + tap];
    g_wt[idx] = __float2half(v);
}

__global__ void wkp_transform(const float* __restrict__ w_kp) {
    int idx = blockIdx.x * 256 + threadIdx.x;
    if (idx >= KKP * CP) return;
    int ci = idx % CP;
    int co = idx / CP;
    float v = 0.f;
    if (co < KK && ci < F) v = w_kp[(size_t)co * F + ci];
    g_wkp[idx] = __float2half(v);
}

// ---------------------------------------------------------------------------
// Input conv 5x5 (3->100) + relu, fp32 FFMA, output fp16 NHWC[112].
// ---------------------------------------------------------------------------
__global__ __launch_bounds__(256)
void conv_in(const float* __restrict__ in, const float* __restrict__ w,
             const float* __restrict__ bias, __half* __restrict__ out) {
    __shared__ float s_in[3][36][37];
    __shared__ float s_w[3][25][10];

    const int t = threadIdx.x;
    const int tx = t & 15, ty = t >> 4;
    const int tileX = (blockIdx.x % 6) * 32;
    const int tileY = (blockIdx.x / 6) * 32;
    const int co0 = blockIdx.y * 10;
    const int b = blockIdx.z;
    const float* inb = in + (size_t)b * 3 * (HW * HW);

    for (int i = t; i < 3 * 36 * 36; i += 256) {
        int cc = i / (36 * 36);
        int rem = i - cc * (36 * 36);
        int r = rem / 36, c = rem - r * 36;
        int gy = tileY + r - 2, gx = tileX + c - 2;
        float v = 0.f;
        if ((unsigned)gy < HW && (unsigned)gx < HW)
            v = inb[(size_t)cc * (HW * HW) + gy * HW + gx];
        s_in[cc][r][c] = v;
    }
    for (int i = t; i < 3 * 250; i += 256) {
        int co = i % 10;
        int tap = (i / 10) % 25;
        int cc = i / 250;
        s_w[cc][tap][co] = w[((size_t)(co0 + co) * 3 + cc) * 25 + tap];
    }
    __syncthreads();

    float acc[10][4];
#pragma unroll
    for (int c = 0; c < 10; c++)
#pragma unroll
        for (int p = 0; p < 4; p++) acc[c][p] = 0.f;

#pragma unroll
    for (int cc = 0; cc < 3; cc++) {
#pragma unroll 1
        for (int ky = 0; ky < 5; ky++) {
            const int r0 = 2 * ty + ky;
#pragma unroll
            for (int kx = 0; kx < 5; kx++) {
                const int c0 = 2 * tx + kx;
                float x00 = s_in[cc][r0][c0];
                float x01 = s_in[cc][r0][c0 + 1];
                float x10 = s_in[cc][r0 + 1][c0];
                float x11 = s_in[cc][r0 + 1][c0 + 1];
                const int tap = ky * 5 + kx;
#pragma unroll
                for (int co = 0; co < 10; co++) {
                    float wv = s_w[cc][tap][co];
                    acc[co][0] = fmaf(wv, x00, acc[co][0]);
                    acc[co][1] = fmaf(wv, x01, acc[co][1]);
                    acc[co][2] = fmaf(wv, x10, acc[co][2]);
                    acc[co][3] = fmaf(wv, x11, acc[co][3]);
                }
            }
        }
    }

#pragma unroll
    for (int co = 0; co < 10; co++) {
        float bb = bias[co0 + co];
#pragma unroll
        for (int p = 0; p < 4; p++) {
            int ly = 2 * ty + (p >> 1);
            int lx = 2 * tx + (p & 1);
            float v = acc[co][p] + bb;
            v = v > 0.f ? v : 0.f;
            out[((size_t)(b * HW + tileY + ly) * HW + tileX + lx) * CP + co0 + co] =
                __float2half(v);
        }
    }
}

// ---------------------------------------------------------------------------
// Hidden conv 5x5 (100->100) + relu, fp16 tensor cores.
// CTA: 256 thr = 8 warps (4 M x 2 N). Tile: 128 couts x 128 pixels (16w x 8h).
// 25 shifted GEMMs; A tile (per-tap weights) double-buffered via cp.async so
// staging of tap t+1 overlaps the MMAs of tap t; one barrier per tap.
// ---------------------------------------------------------------------------
__global__ __launch_bounds__(256, 2)
void conv_hidden(const __half* __restrict__ act_in, const __half* __restrict__ wt,
                 const float* __restrict__ bias, __half* __restrict__ act_out) {
    extern __shared__ __half smem[];
    __half* s_patch = smem;                     // 240 pixel slots * PP halves = 53760 B
    __half* s_A = smem + 240 * PP;              // 2 buffers * 128 * PP = 57344 B
    const uint32_t A_BYTES = 128 * PP * 2;      // 28672

    const int t = threadIdx.x;
    const int lane = t & 31, w = t >> 5;
    const int mw = w & 3, nw = w >> 2;
    const int g = lane >> 2, tg = lane & 3;
    const int tileX = (blockIdx.x % 12) * 16;
    const int tileY = (blockIdx.x / 12) * 8;
    const int b = blockIdx.z;
    const int co0 = mw * 32;

    const uint32_t sp = smem_u32(s_patch);
    const uint32_t sA0 = smem_u32(s_A);

    // Stage input patch via cp.async (zfill at borders): 12x20 pixels x 112 ch.
    {
        const __half* actb = act_in + (size_t)b * HW * HW * CP;
        for (int i = t; i < 240 * 14; i += 256) {
            int pix = i / 14, j = i % 14;
            int r = pix / 20, c = pix % 20;
            int gy = tileY + r - 2, gx = tileX + c - 2;
            bool ok = (unsigned)gy < HW && (unsigned)gx < HW;
            const char* src = ok
                ? (const char*)&actb[((size_t)gy * HW + gx) * CP] + j * 16
                : (const char*)actb;
            cp16z(sp + (uint32_t)pix * (PP * 2) + j * 16, src, ok ? 16 : 0);
        }
    }
    // Prologue: stage A for tap 0 into buffer 0 (contiguous 28672 B).
    {
        const char* wsrc = (const char*)wt;
        for (int i = t; i < 1792; i += 256)
            cp16(sA0 + (uint32_t)i * 16, wsrc + (size_t)i * 16);
    }
    cp_commit();

    // Precompute ldmatrix base addresses (buffer 0; buffer 1 = +A_BYTES).
    uint32_t a_base[2];
#pragma unroll
    for (int mi = 0; mi < 2; mi++)
        a_base[mi] = sA0 + ((co0 + mi * 16 + (lane & 15)) * PP + (lane >> 4) * 8) * 2;

    uint32_t b_base[4];
    {
        int sub = lane >> 3, pix = lane & 7;
#pragma unroll
        for (int j = 0; j < 4; j++) {
            int ni = 2 * j + (sub >> 1);
            int khalf = sub & 1;
            int pr0 = nw * 4 + (ni >> 1);
            int pc0 = (ni & 1) * 8 + pix;
            b_base[j] = sp + ((pr0 * 20 + pc0) * PP + khalf * 8) * 2;
        }
    }

    float acc[2][8][4];
#pragma unroll
    for (int mi = 0; mi < 2; mi++)
#pragma unroll
        for (int ni = 0; ni < 8; ni++)
#pragma unroll
            for (int p = 0; p < 4; p++) acc[mi][ni][p] = 0.f;

    cp_wait<0>();
    __syncthreads();

#pragma unroll 1
    for (int tap = 0; tap < 25; tap++) {
        // Prefetch next tap's A tile into the other buffer.
        if (tap < 24) {
            const char* wsrc = (const char*)(wt + (size_t)(tap + 1) * 128 * PP);
            uint32_t dst = sA0 + ((tap + 1) & 1) * A_BYTES;
            for (int i = t; i < 1792; i += 256)
                cp16(dst + (uint32_t)i * 16, wsrc + (size_t)i * 16);
            cp_commit();
        }

        const uint32_t aoff = (tap & 1) * A_BYTES;
        const int ky = tap / 5, kx = tap % 5;
        const uint32_t tapoff = (uint32_t)(ky * 20 + kx) * (PP * 2);

#pragma unroll
        for (int kc = 0; kc < CP; kc += 16) {
            uint32_t a[2][4];
#pragma unroll
            for (int mi = 0; mi < 2; mi++) ldm_x4(a[mi], a_base[mi] + aoff + kc * 2);
            uint32_t bf[8][2];
#pragma unroll
            for (int j = 0; j < 4; j++) {
                uint32_t r[4];
                ldm_x4(r, b_base[j] + tapoff + kc * 2);
                bf[2 * j][0] = r[0]; bf[2 * j][1] = r[1];
                bf[2 * j + 1][0] = r[2]; bf[2 * j + 1][1] = r[3];
            }
#pragma unroll
            for (int mi = 0; mi < 2; mi++)
#pragma unroll
                for (int ni = 0; ni < 8; ni++)
                    mma16816(acc[mi][ni], a[mi], bf[ni]);
        }

        if (tap < 24) {
            cp_wait<0>();
            __syncthreads();
        }
    }

    // Writeback: bias + relu -> fp16 NHWC (co < 100 only; pad stays zero).
#pragma unroll
    for (int mi = 0; mi < 2; mi++) {
        int co_a = co0 + mi * 16 + g;
        int co_b = co_a + 8;
        float ba = (co_a < F) ? bias[co_a] : 0.f;
        float bb = (co_b < F) ? bias[co_b] : 0.f;
#pragma unroll
        for (int ni = 0; ni < 8; ni++) {
            int py = tileY + nw * 4 + (ni >> 1);
            int px = tileX + ((ni & 1) << 3) + 2 * tg;
            size_t base = ((size_t)(b * HW + py) * HW + px) * CP;
            if (co_a < F) {
                float v0 = acc[mi][ni][0] + ba; v0 = v0 > 0.f ? v0 : 0.f;
                float v1 = acc[mi][ni][1] + ba; v1 = v1 > 0.f ? v1 : 0.f;
                act_out[base + co_a] = __float2half(v0);
                act_out[base + CP + co_a] = __float2half(v1);
            }
            if (co_b < F) {
                float v2 = acc[mi][ni][2] + bb; v2 = v2 > 0.f ? v2 : 0.f;
                float v3 = acc[mi][ni][3] + bb; v3 = v3 > 0.f ? v3 : 0.f;
                act_out[base + co_b] = __float2half(v2);
                act_out[base + CP + co_b] = __float2half(v3);
            }
        }
    }
}

// ---------------------------------------------------------------------------
// kp GEMM: logits[px][448] = wkp[448][112] x feat[px][112], fp16 tensor cores.
// Tile: 128 logit rows x 128 pixels (16w x 8h), no halo, single "tap".
// ---------------------------------------------------------------------------
__global__ __launch_bounds__(256, 2)
void kp_gemm(const __half* __restrict__ feat, const __half* __restrict__ wkp,
             const float* __restrict__ b_kp, __half* __restrict__ logits) {
    extern __shared__ __half smem[];
    __half* s_px = smem;                  // 128 * PITCH
    __half* s_A = smem + 128 * PITCH;     // 128 * PITCH

    const int t = threadIdx.x;
    const int lane = t & 31, w = t >> 5;
    const int mw = w & 3, nw = w >> 2;
    const int g = lane >> 2, tg = lane & 3;
    const int tileX = (blockIdx.x % 12) * 16;
    const int tileY = (blockIdx.x / 12) * 8;
    const int co0g = blockIdx.y * 128;
    const int b = blockIdx.z;
    const int co0 = mw * 32;

    {
        const __half* fb = feat + (size_t)b * HW * HW * CP;
        for (int i = t; i < 128 * 14; i += 256) {
            int pix = i / 14, j = i % 14;
            int gy = tileY + pix / 16, gx = tileX + (pix & 15);
            ((uint4*)&s_px[pix * PITCH])[j] =
                ((const uint4*)&fb[((size_t)gy * HW + gx) * CP])[j];
        }
        for (int i = t; i < 128 * 14; i += 256) {
            int co = i / 14, j = i % 14;
            uint4 v = make_uint4(0, 0, 0, 0);
            if (co0g + co < KKP)
                v = ((const uint4*)&wkp[(size_t)(co0g + co) * CP])[j];
            ((uint4*)&s_A[co * PITCH])[j] = v;
        }
    }
    __syncthreads();

    uint32_t a_base[2];
#pragma unroll
    for (int mi = 0; mi < 2; mi++)
        a_base[mi] = smem_u32(&s_A[(co0 + mi * 16 + (lane & 15)) * PITCH + (lane >> 4) * 8]);
    uint32_t b_base[4];
    {
        int sub = lane >> 3, pix = lane & 7;
#pragma unroll
        for (int j = 0; j < 4; j++) {
            int ni = 2 * j + (sub >> 1);
            int khalf = sub & 1;
            int pr0 = nw * 4 + (ni >> 1);
            int pc0 = (ni & 1) * 8 + pix;
            b_base[j] = smem_u32(&s_px[(pr0 * 16 + pc0) * PITCH + khalf * 8]);
        }
    }

    float acc[2][8][4];
#pragma unroll
    for (int mi = 0; mi < 2; mi++)
#pragma unroll
        for (int ni = 0; ni < 8; ni++)
#pragma unroll
            for (int p = 0; p < 4; p++) acc[mi][ni][p] = 0.f;

#pragma unroll
    for (int kc = 0; kc < CP; kc += 16) {
        uint32_t a[2][4];
#pragma unroll
        for (int mi = 0; mi < 2; mi++) ldm_x4(a[mi], a_base[mi] + kc * 2);
        uint32_t bf[8][2];
#pragma unroll
        for (int j = 0; j < 4; j++) {
            uint32_t r[4];
            ldm_x4(r, b_base[j] + kc * 2);
            bf[2 * j][0] = r[0]; bf[2 * j][1] = r[1];
            bf[2 * j + 1][0] = r[2]; bf[2 * j + 1][1] = r[3];
        }
#pragma unroll
        for (int mi = 0; mi < 2; mi++)
#pragma unroll
            for (int ni = 0; ni < 8; ni++)
                mma16816(acc[mi][ni], a[mi], bf[ni]);
    }

#pragma unroll
    for (int mi = 0; mi < 2; mi++) {
        int co_a = co0g + co0 + mi * 16 + g;
        int co_b = co_a + 8;
        float ba = (co_a < KK) ? b_kp[co_a] : 0.f;
        float bb = (co_b < KK) ? b_kp[co_b] : 0.f;
#pragma unroll
        for (int ni = 0; ni < 8; ni++) {
            int py = tileY + nw * 4 + (ni >> 1);
            int px = tileX + ((ni & 1) << 3) + 2 * tg;
            size_t base = ((size_t)(b * HW + py) * HW + px) * KKP;
            if (co_a < KK) {
                logits[base + co_a] = __float2half(acc[mi][ni][0] + ba);
                logits[base + KKP + co_a] = __float2half(acc[mi][ni][1] + ba);
            }
            if (co_b < KK) {
                logits[base + co_b] = __float2half(acc[mi][ni][2] + bb);
                logits[base + KKP + co_b] = __float2half(acc[mi][ni][3] + bb);
            }
        }
    }
}

// ---------------------------------------------------------------------------
// Softmax + 21x21 kernel apply. Warp per pixel, 8 pixels per block (one x-run).
// ---------------------------------------------------------------------------
__global__ __launch_bounds__(256)
void kp_apply(const __half* __restrict__ logits, const float* __restrict__ noisy,
              float* __restrict__ out) {
    __shared__ float s_patch[3][21][28];

    const int t = threadIdx.x;
    const int lane = t & 31, wid = t >> 5;
    const int x0 = blockIdx.x * 8;
    const int y = blockIdx.y;
    const int b = blockIdx.z;

    for (int i = t; i < 3 * 21 * 28; i += 256) {
        int c = i / (21 * 28);
        int rem = i - c * (21 * 28);
        int dy = rem / 28, dx = rem - dy * 28;
        int gy = y + dy - 10, gx = x0 + dx - 10;
        float v = 0.f;
        if ((unsigned)gy < HW && (unsigned)gx < HW)
            v = noisy[(((size_t)b * 3 + c) * HW + gy) * HW + gx];
        s_patch[c][dy][dx] = v;
    }
    __syncthreads();

    const __half* lp = logits + ((size_t)(b * HW + y) * HW + x0 + wid) * KKP;
    float L[14];
#pragma unroll
    for (int i = 0; i < 14; i++) {
        int j = i * 32 + lane;
        L[i] = (j < KK) ? __half2float(lp[j]) : -1e30f;
    }
    float m = -1e30f;
#pragma unroll
    for (int i = 0; i < 14; i++) m = fmaxf(m, L[i]);
#pragma unroll
    for (int o = 16; o; o >>= 1) m = fmaxf(m, __shfl_xor_sync(0xffffffffu, m, o));

    float se = 0.f, o0 = 0.f, o1 = 0.f, o2 = 0.f;
#pragma unroll
    for (int i = 0; i < 14; i++) {
        int j = i * 32 + lane;
        if (j < KK) {
            float e = __expf(L[i] - m);
            int ky = j / 21, kx = j - ky * 21;
            se += e;
            o0 += e * s_patch[0][ky][kx + wid];
            o1 += e * s_patch[1][ky][kx + wid];
            o2 += e * s_patch[2][ky][kx + wid];
        }
    }
#pragma unroll
    for (int o = 16; o; o >>= 1) {
        se += __shfl_xor_sync(0xffffffffu, se, o);
        o0 += __shfl_xor_sync(0xffffffffu, o0, o);
        o1 += __shfl_xor_sync(0xffffffffu, o1, o);
        o2 += __shfl_xor_sync(0xffffffffu, o2, o);
    }
    if (lane == 0) {
        float inv = 1.f / se;
        out[(((size_t)b * 3 + 0) * HW + y) * HW + x0 + wid] = o0 * inv;
        out[(((size_t)b * 3 + 1) * HW + y) * HW + x0 + wid] = o1 * inv;
        out[(((size_t)b * 3 + 2) * HW + y) * HW + x0 + wid] = o2 * inv;
    }
}

// ---------------------------------------------------------------------------
extern "C" void kernel_launch(void* const* d_in, const int* in_sizes, int n_in,
                              void* d_out, int out_size) {
    const float* noisy = (const float*)d_in[0];
    const float* w_in  = (const float*)d_in[1];
    const float* b_in  = (const float*)d_in[2];
    const float* w_hid = (const float*)d_in[3];
    const float* b_hid = (const float*)d_in[4];
    const float* w_kp  = (const float*)d_in[5];
    const float* b_kp  = (const float*)d_in[6];
    float* out = (float*)d_out;

    __half *act0, *act1, *wt, *wkp, *logits;
    cudaGetSymbolAddress((void**)&act0, g_act0);
    cudaGetSymbolAddress((void**)&act1, g_act1);
    cudaGetSymbolAddress((void**)&wt, g_wt);
    cudaGetSymbolAddress((void**)&wkp, g_wkp);
    cudaGetSymbolAddress((void**)&logits, g_logits);

    const int smem_hidden = 240 * PP * 2 + 2 * 128 * PP * 2;  // 53760 + 57344 = 111104 B
    const int smem_kp = 2 * 128 * PITCH * 2;                  // 61440 B
    cudaFuncSetAttribute(conv_hidden, cudaFuncAttributeMaxDynamicSharedMemorySize,
                         smem_hidden);
    cudaFuncSetAttribute(kp_gemm, cudaFuncAttributeMaxDynamicSharedMemorySize,
                         smem_kp);

    const size_t actBytes = (size_t)2 * HW * HW * CP * sizeof(__half);
    cudaMemsetAsync(act0, 0, actBytes);
    cudaMemsetAsync(act1, 0, actBytes);

    wt_transform<<<(7 * 25 * 128 * CP + 255) / 256, 256>>>(w_hid);
    wkp_transform<<<(KKP * CP + 255) / 256, 256>>>(w_kp);

    conv_in<<<dim3(36, 10, 2), 256>>>(noisy, w_in, b_in, act0);

    const __half* src = act0;
    __half* dst = act1;
    for (int l = 0; l < 7; l++) {
        conv_hidden<<<dim3(288, 1, 2), 256, smem_hidden>>>(
            src, wt + (size_t)l * 25 * 128 * CP, b_hid + l * F, dst);
        __half* tmp = (__half*)src;
        src = dst;
        dst = tmp;
    }

    kp_gemm<<<dim3(288, 4, 2), 256, smem_kp>>>(src, wkp, b_kp, logits);
    kp_apply<<<dim3(24, HW, 2), 256>>>(logits, noisy, out);
}

// round 9
// speedup vs baseline: 1.3080x; 1.3080x over previous
#include <cuda_runtime.h>
#include <cuda_fp16.h>
#include <cstdint>

#define HW 192
#define F 100
#define CP 112            // padded channel count (stored)
#define PP 112            // conv_hidden smem pitch in halves (224B; XOR-swizzled -> conflict-free)
#define PITCH 120         // kp_gemm smem pitch (conflict-free)
#define KK 441
#define KKP 448           // padded logit count

// Activation ping-pong buffers: fp16 NHWC[112]: 2*192*192*112 halves = 16.5 MB each.
__device__ __half g_act0[2 * HW * HW * CP];
__device__ __half g_act1[2 * HW * HW * CP];
// Transformed hidden weights: [layer7][tap25][co128][ci112] fp16, 16B-chunk swizzled.
__device__ __half g_wt[7 * 25 * 128 * CP];
// Transformed kp weights: [448][112] fp16.
__device__ __half g_wkp[KKP * CP];
// Logits: [b][y][x][448] fp16 = 66 MB.
__device__ __half g_logits[2 * HW * HW * KKP];

// ---------------------------------------------------------------------------
// PTX helpers
// ---------------------------------------------------------------------------
__device__ __forceinline__ uint32_t smem_u32(const void* p) {
    return (uint32_t)__cvta_generic_to_shared(p);
}
__device__ __forceinline__ void ldm_x4(uint32_t* r, uint32_t addr) {
    asm volatile("ldmatrix.sync.aligned.m8n8.x4.shared.b16 {%0,%1,%2,%3}, [%4];"
                 : "=r"(r[0]), "=r"(r[1]), "=r"(r[2]), "=r"(r[3]) : "r"(addr));
}
__device__ __forceinline__ void mma16816(float* c, const uint32_t* a, const uint32_t* b) {
    asm volatile(
        "mma.sync.aligned.m16n8k16.row.col.f32.f16.f16.f32 "
        "{%0,%1,%2,%3}, {%4,%5,%6,%7}, {%8,%9}, {%0,%1,%2,%3};"
        : "+f"(c[0]), "+f"(c[1]), "+f"(c[2]), "+f"(c[3])
        : "r"(a[0]), "r"(a[1]), "r"(a[2]), "r"(a[3]), "r"(b[0]), "r"(b[1]));
}
__device__ __forceinline__ void cp16(uint32_t dst, const void* src) {
    asm volatile("cp.async.cg.shared.global [%0], [%1], 16;" :: "r"(dst), "l"(src));
}
__device__ __forceinline__ void cp16z(uint32_t dst, const void* src, int srcsz) {
    asm volatile("cp.async.cg.shared.global [%0], [%1], 16, %2;"
                 :: "r"(dst), "l"(src), "r"(srcsz));
}
__device__ __forceinline__ void cp_commit() {
    asm volatile("cp.async.commit_group;");
}
template <int N>
__device__ __forceinline__ void cp_wait() {
    asm volatile("cp.async.wait_group %0;" :: "n"(N));
}

// ---------------------------------------------------------------------------
// Weight transforms. g_wt rows are 16B-chunk swizzled: for rows with
// (co>>2)&1 == 1, the half-index is XORed with 8 (16 bytes), making all 8
// LDSM octet addresses (row stride 224B) land on distinct 16B banks mod 128B.
// ---------------------------------------------------------------------------
__global__ void wt_transform(const float* __restrict__ w_hid) {
    int idx = blockIdx.x * 256 + threadIdx.x;
    if (idx >= 7 * 25 * 128 * CP) return;
    int ci_out = idx % CP;
    int co = (idx / CP) % 128;
    int tap = (idx / (CP * 128)) % 25;
    int l = idx / (CP * 128 * 25);
    int ci = ((co >> 2) & 1) ? (ci_out ^ 8) : ci_out;   // inverse of placement XOR
    float v = 0.f;
    if (co < F && ci < F)
        v = w_hid[(((size_t)l * F + co) * F + ci) * 25 + tap];
    g_wt[idx] = __float2half(v);
}

__global__ void wkp_transform(const float* __restrict__ w_kp) {
    int idx = blockIdx.x * 256 + threadIdx.x;
    if (idx >= KKP * CP) return;
    int ci = idx % CP;
    int co = idx / CP;
    float v = 0.f;
    if (co < KK && ci < F) v = w_kp[(size_t)co * F + ci];
    g_wkp[idx] = __float2half(v);
}

// ---------------------------------------------------------------------------
// Input conv 5x5 (3->100) + relu, fp32 FFMA, output fp16 NHWC[112].
// ---------------------------------------------------------------------------
__global__ __launch_bounds__(256)
void conv_in(const float* __restrict__ in, const float* __restrict__ w,
             const float* __restrict__ bias, __half* __restrict__ out) {
    __shared__ float s_in[3][36][37];
    __shared__ float s_w[3][25][10];

    const int t = threadIdx.x;
    const int tx = t & 15, ty = t >> 4;
    const int tileX = (blockIdx.x % 6) * 32;
    const int tileY = (blockIdx.x / 6) * 32;
    const int co0 = blockIdx.y * 10;
    const int b = blockIdx.z;
    const float* inb = in + (size_t)b * 3 * (HW * HW);

    for (int i = t; i < 3 * 36 * 36; i += 256) {
        int cc = i / (36 * 36);
        int rem = i - cc * (36 * 36);
        int r = rem / 36, c = rem - r * 36;
        int gy = tileY + r - 2, gx = tileX + c - 2;
        float v = 0.f;
        if ((unsigned)gy < HW && (unsigned)gx < HW)
            v = inb[(size_t)cc * (HW * HW) + gy * HW + gx];
        s_in[cc][r][c] = v;
    }
    for (int i = t; i < 3 * 250; i += 256) {
        int co = i % 10;
        int tap = (i / 10) % 25;
        int cc = i / 250;
        s_w[cc][tap][co] = w[((size_t)(co0 + co) * 3 + cc) * 25 + tap];
    }
    __syncthreads();

    float acc[10][4];
#pragma unroll
    for (int c = 0; c < 10; c++)
#pragma unroll
        for (int p = 0; p < 4; p++) acc[c][p] = 0.f;

#pragma unroll
    for (int cc = 0; cc < 3; cc++) {
#pragma unroll 1
        for (int ky = 0; ky < 5; ky++) {
            const int r0 = 2 * ty + ky;
#pragma unroll
            for (int kx = 0; kx < 5; kx++) {
                const int c0 = 2 * tx + kx;
                float x00 = s_in[cc][r0][c0];
                float x01 = s_in[cc][r0][c0 + 1];
                float x10 = s_in[cc][r0 + 1][c0];
                float x11 = s_in[cc][r0 + 1][c0 + 1];
                const int tap = ky * 5 + kx;
#pragma unroll
                for (int co = 0; co < 10; co++) {
                    float wv = s_w[cc][tap][co];
                    acc[co][0] = fmaf(wv, x00, acc[co][0]);
                    acc[co][1] = fmaf(wv, x01, acc[co][1]);
                    acc[co][2] = fmaf(wv, x10, acc[co][2]);
                    acc[co][3] = fmaf(wv, x11, acc[co][3]);
                }
            }
        }
    }

#pragma unroll
    for (int co = 0; co < 10; co++) {
        float bb = bias[co0 + co];
#pragma unroll
        for (int p = 0; p < 4; p++) {
            int ly = 2 * ty + (p >> 1);
            int lx = 2 * tx + (p & 1);
            float v = acc[co][p] + bb;
            v = v > 0.f ? v : 0.f;
            out[((size_t)(b * HW + tileY + ly) * HW + tileX + lx) * CP + co0 + co] =
                __float2half(v);
        }
    }
}

// ---------------------------------------------------------------------------
// Hidden conv 5x5 (100->100) + relu, fp16 tensor cores.
// CTA: 256 thr = 8 warps (4 M x 2 N). Tile: 128 couts x 128 pixels (16w x 8h).
// 25 shifted GEMMs; A double-buffered via cp.async (one barrier per tap).
// Both smem operands use the XOR-16B chunk swizzle -> conflict-free LDSM.
// ---------------------------------------------------------------------------
__global__ __launch_bounds__(256, 2)
void conv_hidden(const __half* __restrict__ act_in, const __half* __restrict__ wt,
                 const float* __restrict__ bias, __half* __restrict__ act_out) {
    extern __shared__ __align__(128) __half smem[];
    __half* s_patch = smem;                     // 240 pixel slots * PP halves = 53760 B
    __half* s_A = smem + 240 * PP;              // 2 buffers * 128 * PP = 57344 B
    const uint32_t A_BYTES = 128 * PP * 2;      // 28672

    const int t = threadIdx.x;
    const int lane = t & 31, w = t >> 5;
    const int mw = w & 3, nw = w >> 2;
    const int g = lane >> 2, tg = lane & 3;
    const int tileX = (blockIdx.x % 12) * 16;
    const int tileY = (blockIdx.x / 12) * 8;
    const int b = blockIdx.z;
    const int co0 = mw * 32;

    const uint32_t sp = smem_u32(s_patch);
    const uint32_t sA0 = smem_u32(s_A);

    // Stage input patch via cp.async (zfill at borders): 12x20 pixels x 112 ch,
    // chunk j of pixel s stored at s*224 + (j*16 ^ ((s>>2&1)<<4)).
    {
        const __half* actb = act_in + (size_t)b * HW * HW * CP;
        for (int i = t; i < 240 * 14; i += 256) {
            int pix = i / 14, j = i % 14;
            int r = pix / 20, c = pix % 20;
            int gy = tileY + r - 2, gx = tileX + c - 2;
            bool ok = (unsigned)gy < HW && (unsigned)gx < HW;
            const char* src = ok
                ? (const char*)&actb[((size_t)gy * HW + gx) * CP] + j * 16
                : (const char*)actb;
            uint32_t dst = sp + (uint32_t)pix * (PP * 2) +
                           ((uint32_t)(j * 16) ^ (((pix >> 2) & 1) << 4));
            cp16z(dst, src, ok ? 16 : 0);
        }
    }
    // Prologue: stage A for tap 0 into buffer 0 (g_wt is pre-swizzled; linear copy).
    {
        const char* wsrc = (const char*)wt;
        for (int i = t; i < 1792; i += 256)
            cp16(sA0 + (uint32_t)i * 16, wsrc + (size_t)i * 16);
    }
    cp_commit();

    // Precompute ldmatrix base addresses (buffer 0; buffer 1 = +A_BYTES).
    uint32_t a_base[2];
#pragma unroll
    for (int mi = 0; mi < 2; mi++) {
        int row = co0 + mi * 16 + (lane & 15);
        uint32_t acol2 = (uint32_t)(lane >> 4) * 16;                // byte offset
        a_base[mi] = sA0 + (uint32_t)row * (PP * 2) +
                     (acol2 ^ (((uint32_t)(row >> 2) & 1) << 4));
    }

    uint32_t b_base[4];
    uint32_t s0pack = 0;
    {
        int sub = lane >> 3, pix = lane & 7;
#pragma unroll
        for (int j = 0; j < 4; j++) {
            int ni = 2 * j + (sub >> 1);
            int khalf = sub & 1;
            int pr0 = nw * 4 + (ni >> 1);
            int pc0 = (ni & 1) * 8 + pix;
            int s0 = pr0 * 20 + pc0;
            b_base[j] = sp + (uint32_t)s0 * (PP * 2) + (uint32_t)khalf * 16;
            s0pack |= (uint32_t)s0 << (8 * j);
        }
    }

    float acc[2][8][4];
#pragma unroll
    for (int mi = 0; mi < 2; mi++)
#pragma unroll
        for (int ni = 0; ni < 8; ni++)
#pragma unroll
            for (int p = 0; p < 4; p++) acc[mi][ni][p] = 0.f;

    cp_wait<0>();
    __syncthreads();

#pragma unroll 1
    for (int tap = 0; tap < 25; tap++) {
        // Prefetch next tap's A tile into the other buffer.
        if (tap < 24) {
            const char* wsrc = (const char*)(wt + (size_t)(tap + 1) * 128 * CP);
            uint32_t dst = sA0 + ((tap + 1) & 1) * A_BYTES;
            for (int i = t; i < 1792; i += 256)
                cp16(dst + (uint32_t)i * 16, wsrc + (size_t)i * 16);
            cp_commit();
        }

        const uint32_t aoff = (tap & 1) * A_BYTES;
        const int ky = tap / 5, kx = tap % 5;
        const int ds = ky * 20 + kx;
        const uint32_t dsb = (uint32_t)ds * (PP * 2);

        // Per-tap B addresses: shifted pixel row s = s0 + ds changes the swizzle bit.
        uint32_t b_tap[4];
#pragma unroll
        for (int j = 0; j < 4; j++) {
            uint32_t s0j = (s0pack >> (8 * j)) & 255u;
            uint32_t swz = ((s0j + (uint32_t)ds) << 2) & 16u;
            b_tap[j] = (b_base[j] + dsb) ^ swz;
        }

#pragma unroll
        for (int kc = 0; kc < CP; kc += 16) {
            uint32_t a[2][4];
#pragma unroll
            for (int mi = 0; mi < 2; mi++) ldm_x4(a[mi], a_base[mi] + aoff + kc * 2);
            uint32_t bf[8][2];
#pragma unroll
            for (int j = 0; j < 4; j++) {
                uint32_t r[4];
                ldm_x4(r, b_tap[j] + kc * 2);
                bf[2 * j][0] = r[0]; bf[2 * j][1] = r[1];
                bf[2 * j + 1][0] = r[2]; bf[2 * j + 1][1] = r[3];
            }
#pragma unroll
            for (int mi = 0; mi < 2; mi++)
#pragma unroll
                for (int ni = 0; ni < 8; ni++)
                    mma16816(acc[mi][ni], a[mi], bf[ni]);
        }

        if (tap < 24) {
            cp_wait<0>();
            __syncthreads();
        }
    }

    // Writeback: bias + relu -> fp16 NHWC (co < 100 only; pad stays zero).
#pragma unroll
    for (int mi = 0; mi < 2; mi++) {
        int co_a = co0 + mi * 16 + g;
        int co_b = co_a + 8;
        float ba = (co_a < F) ? bias[co_a] : 0.f;
        float bb = (co_b < F) ? bias[co_b] : 0.f;
#pragma unroll
        for (int ni = 0; ni < 8; ni++) {
            int py = tileY + nw * 4 + (ni >> 1);
            int px = tileX + ((ni & 1) << 3) + 2 * tg;
            size_t base = ((size_t)(b * HW + py) * HW + px) * CP;
            if (co_a < F) {
                float v0 = acc[mi][ni][0] + ba; v0 = v0 > 0.f ? v0 : 0.f;
                float v1 = acc[mi][ni][1] + ba; v1 = v1 > 0.f ? v1 : 0.f;
                act_out[base + co_a] = __float2half(v0);
                act_out[base + CP + co_a] = __float2half(v1);
            }
            if (co_b < F) {
                float v2 = acc[mi][ni][2] + bb; v2 = v2 > 0.f ? v2 : 0.f;
                float v3 = acc[mi][ni][3] + bb; v3 = v3 > 0.f ? v3 : 0.f;
                act_out[base + co_b] = __float2half(v2);
                act_out[base + CP + co_b] = __float2half(v3);
            }
        }
    }
}

// ---------------------------------------------------------------------------
// kp GEMM: logits[px][448] = wkp[448][112] x feat[px][112], fp16 tensor cores.
// Tile: 128 logit rows x 128 pixels (16w x 8h), pitch 120 (conflict-free).
// ---------------------------------------------------------------------------
__global__ __launch_bounds__(256, 2)
void kp_gemm(const __half* __restrict__ feat, const __half* __restrict__ wkp,
             const float* __restrict__ b_kp, __half* __restrict__ logits) {
    extern __shared__ __align__(128) __half smem[];
    __half* s_px = smem;                  // 128 * PITCH
    __half* s_A = smem + 128 * PITCH;     // 128 * PITCH

    const int t = threadIdx.x;
    const int lane = t & 31, w = t >> 5;
    const int mw = w & 3, nw = w >> 2;
    const int g = lane >> 2, tg = lane & 3;
    const int tileX = (blockIdx.x % 12) * 16;
    const int tileY = (blockIdx.x / 12) * 8;
    const int co0g = blockIdx.y * 128;
    const int b = blockIdx.z;
    const int co0 = mw * 32;

    {
        const __half* fb = feat + (size_t)b * HW * HW * CP;
        for (int i = t; i < 128 * 14; i += 256) {
            int pix = i / 14, j = i % 14;
            int gy = tileY + pix / 16, gx = tileX + (pix & 15);
            ((uint4*)&s_px[pix * PITCH])[j] =
                ((const uint4*)&fb[((size_t)gy * HW + gx) * CP])[j];
        }
        for (int i = t; i < 128 * 14; i += 256) {
            int co = i / 14, j = i % 14;
            uint4 v = make_uint4(0, 0, 0, 0);
            if (co0g + co < KKP)
                v = ((const uint4*)&wkp[(size_t)(co0g + co) * CP])[j];
            ((uint4*)&s_A[co * PITCH])[j] = v;
        }
    }
    __syncthreads();

    uint32_t a_base[2];
#pragma unroll
    for (int mi = 0; mi < 2; mi++)
        a_base[mi] = smem_u32(&s_A[(co0 + mi * 16 + (lane & 15)) * PITCH + (lane >> 4) * 8]);
    uint32_t b_base[4];
    {
        int sub = lane >> 3, pix = lane & 7;
#pragma unroll
        for (int j = 0; j < 4; j++) {
            int ni = 2 * j + (sub >> 1);
            int khalf = sub & 1;
            int pr0 = nw * 4 + (ni >> 1);
            int pc0 = (ni & 1) * 8 + pix;
            b_base[j] = smem_u32(&s_px[(pr0 * 16 + pc0) * PITCH + khalf * 8]);
        }
    }

    float acc[2][8][4];
#pragma unroll
    for (int mi = 0; mi < 2; mi++)
#pragma unroll
        for (int ni = 0; ni < 8; ni++)
#pragma unroll
            for (int p = 0; p < 4; p++) acc[mi][ni][p] = 0.f;

#pragma unroll
    for (int kc = 0; kc < CP; kc += 16) {
        uint32_t a[2][4];
#pragma unroll
        for (int mi = 0; mi < 2; mi++) ldm_x4(a[mi], a_base[mi] + kc * 2);
        uint32_t bf[8][2];
#pragma unroll
        for (int j = 0; j < 4; j++) {
            uint32_t r[4];
            ldm_x4(r, b_base[j] + kc * 2);
            bf[2 * j][0] = r[0]; bf[2 * j][1] = r[1];
            bf[2 * j + 1][0] = r[2]; bf[2 * j + 1][1] = r[3];
        }
#pragma unroll
        for (int mi = 0; mi < 2; mi++)
#pragma unroll
            for (int ni = 0; ni < 8; ni++)
                mma16816(acc[mi][ni], a[mi], bf[ni]);
    }

#pragma unroll
    for (int mi = 0; mi < 2; mi++) {
        int co_a = co0g + co0 + mi * 16 + g;
        int co_b = co_a + 8;
        float ba = (co_a < KK) ? b_kp[co_a] : 0.f;
        float bb = (co_b < KK) ? b_kp[co_b] : 0.f;
#pragma unroll
        for (int ni = 0; ni < 8; ni++) {
            int py = tileY + nw * 4 + (ni >> 1);
            int px = tileX + ((ni & 1) << 3) + 2 * tg;
            size_t base = ((size_t)(b * HW + py) * HW + px) * KKP;
            if (co_a < KK) {
                logits[base + co_a] = __float2half(acc[mi][ni][0] + ba);
                logits[base + KKP + co_a] = __float2half(acc[mi][ni][1] + ba);
            }
            if (co_b < KK) {
                logits[base + co_b] = __float2half(acc[mi][ni][2] + bb);
                logits[base + KKP + co_b] = __float2half(acc[mi][ni][3] + bb);
            }
        }
    }
}

// ---------------------------------------------------------------------------
// Softmax + 21x21 kernel apply. Warp per pixel, 8 pixels per block (one x-run).
// ---------------------------------------------------------------------------
__global__ __launch_bounds__(256)
void kp_apply(const __half* __restrict__ logits, const float* __restrict__ noisy,
              float* __restrict__ out) {
    __shared__ float s_patch[3][21][28];

    const int t = threadIdx.x;
    const int lane = t & 31, wid = t >> 5;
    const int x0 = blockIdx.x * 8;
    const int y = blockIdx.y;
    const int b = blockIdx.z;

    for (int i = t; i < 3 * 21 * 28; i += 256) {
        int c = i / (21 * 28);
        int rem = i - c * (21 * 28);
        int dy = rem / 28, dx = rem - dy * 28;
        int gy = y + dy - 10, gx = x0 + dx - 10;
        float v = 0.f;
        if ((unsigned)gy < HW && (unsigned)gx < HW)
            v = noisy[(((size_t)b * 3 + c) * HW + gy) * HW + gx];
        s_patch[c][dy][dx] = v;
    }
    __syncthreads();

    const __half* lp = logits + ((size_t)(b * HW + y) * HW + x0 + wid) * KKP;
    float L[14];
#pragma unroll
    for (int i = 0; i < 14; i++) {
        int j = i * 32 + lane;
        L[i] = (j < KK) ? __half2float(lp[j]) : -1e30f;
    }
    float m = -1e30f;
#pragma unroll
    for (int i = 0; i < 14; i++) m = fmaxf(m, L[i]);
#pragma unroll
    for (int o = 16; o; o >>= 1) m = fmaxf(m, __shfl_xor_sync(0xffffffffu, m, o));

    float se = 0.f, o0 = 0.f, o1 = 0.f, o2 = 0.f;
#pragma unroll
    for (int i = 0; i < 14; i++) {
        int j = i * 32 + lane;
        if (j < KK) {
            float e = __expf(L[i] - m);
            int ky = j / 21, kx = j - ky * 21;
            se += e;
            o0 += e * s_patch[0][ky][kx + wid];
            o1 += e * s_patch[1][ky][kx + wid];
            o2 += e * s_patch[2][ky][kx + wid];
        }
    }
#pragma unroll
    for (int o = 16; o; o >>= 1) {
        se += __shfl_xor_sync(0xffffffffu, se, o);
        o0 += __shfl_xor_sync(0xffffffffu, o0, o);
        o1 += __shfl_xor_sync(0xffffffffu, o1, o);
        o2 += __shfl_xor_sync(0xffffffffu, o2, o);
    }
    if (lane == 0) {
        float inv = 1.f / se;
        out[(((size_t)b * 3 + 0) * HW + y) * HW + x0 + wid] = o0 * inv;
        out[(((size_t)b * 3 + 1) * HW + y) * HW + x0 + wid] = o1 * inv;
        out[(((size_t)b * 3 + 2) * HW + y) * HW + x0 + wid] = o2 * inv;
    }
}

// ---------------------------------------------------------------------------
extern "C" void kernel_launch(void* const* d_in, const int* in_sizes, int n_in,
                              void* d_out, int out_size) {
    const float* noisy = (const float*)d_in[0];
    const float* w_in  = (const float*)d_in[1];
    const float* b_in  = (const float*)d_in[2];
    const float* w_hid = (const float*)d_in[3];
    const float* b_hid = (const float*)d_in[4];
    const float* w_kp  = (const float*)d_in[5];
    const float* b_kp  = (const float*)d_in[6];
    float* out = (float*)d_out;

    __half *act0, *act1, *wt, *wkp, *logits;
    cudaGetSymbolAddress((void**)&act0, g_act0);
    cudaGetSymbolAddress((void**)&act1, g_act1);
    cudaGetSymbolAddress((void**)&wt, g_wt);
    cudaGetSymbolAddress((void**)&wkp, g_wkp);
    cudaGetSymbolAddress((void**)&logits, g_logits);

    const int smem_hidden = 240 * PP * 2 + 2 * 128 * PP * 2;  // 53760 + 57344 = 111104 B
    const int smem_kp = 2 * 128 * PITCH * 2;                  // 61440 B
    cudaFuncSetAttribute(conv_hidden, cudaFuncAttributeMaxDynamicSharedMemorySize,
                         smem_hidden);
    cudaFuncSetAttribute(kp_gemm, cudaFuncAttributeMaxDynamicSharedMemorySize,
                         smem_kp);

    const size_t actBytes = (size_t)2 * HW * HW * CP * sizeof(__half);
    cudaMemsetAsync(act0, 0, actBytes);
    cudaMemsetAsync(act1, 0, actBytes);

    wt_transform<<<(7 * 25 * 128 * CP + 255) / 256, 256>>>(w_hid);
    wkp_transform<<<(KKP * CP + 255) / 256, 256>>>(w_kp);

    conv_in<<<dim3(36, 10, 2), 256>>>(noisy, w_in, b_in, act0);

    const __half* src = act0;
    __half* dst = act1;
    for (int l = 0; l < 7; l++) {
        conv_hidden<<<dim3(288, 1, 2), 256, smem_hidden>>>(
            src, wt + (size_t)l * 25 * 128 * CP, b_hid + l * F, dst);
        __half* tmp = (__half*)src;
        src = dst;
        dst = tmp;
    }

    kp_gemm<<<dim3(288, 4, 2), 256, smem_kp>>>(src, wkp, b_kp, logits);
    kp_apply<<<dim3(24, HW, 2), 256>>>(logits, noisy, out);
}

// round 11
// speedup vs baseline: 1.3510x; 1.0329x over previous
#include <cuda_runtime.h>
#include <cuda_fp16.h>
#include <cstdint>

#define HW 192
#define F 100
#define CP 112            // padded channel count (stored)
#define PP 112            // conv_hidden smem pitch in halves (224B; XOR-swizzled -> conflict-free)
#define PITCH 120         // kp smem pitch (conflict-free)
#define KK 441
#define KKP 448
#define LGP 66            // logits smem pitch in halves (132B -> lane-conflict-free reads)

// Activation ping-pong buffers: fp16 NHWC[112]: 2*192*192*112 halves = 16.5 MB each.
__device__ __half g_act0[2 * HW * HW * CP];
__device__ __half g_act1[2 * HW * HW * CP];
// Transformed hidden weights: [layer7][tap25][co128][ci112] fp16, 16B-chunk swizzled.
__device__ __half g_wt[7 * 25 * 128 * CP];
// Transformed kp weights: [448][112] fp16.
__device__ __half g_wkp[KKP * CP];

// ---------------------------------------------------------------------------
// PTX helpers
// ---------------------------------------------------------------------------
__device__ __forceinline__ uint32_t smem_u32(const void* p) {
    return (uint32_t)__cvta_generic_to_shared(p);
}
__device__ __forceinline__ void ldm_x4(uint32_t* r, uint32_t addr) {
    asm volatile("ldmatrix.sync.aligned.m8n8.x4.shared.b16 {%0,%1,%2,%3}, [%4];"
                 : "=r"(r[0]), "=r"(r[1]), "=r"(r[2]), "=r"(r[3]) : "r"(addr));
}
__device__ __forceinline__ void mma16816(float* c, const uint32_t* a, const uint32_t* b) {
    asm volatile(
        "mma.sync.aligned.m16n8k16.row.col.f32.f16.f16.f32 "
        "{%0,%1,%2,%3}, {%4,%5,%6,%7}, {%8,%9}, {%0,%1,%2,%3};"
        : "+f"(c[0]), "+f"(c[1]), "+f"(c[2]), "+f"(c[3])
        : "r"(a[0]), "r"(a[1]), "r"(a[2]), "r"(a[3]), "r"(b[0]), "r"(b[1]));
}
__device__ __forceinline__ void cp16(uint32_t dst, const void* src) {
    asm volatile("cp.async.cg.shared.global [%0], [%1], 16;" :: "r"(dst), "l"(src));
}
__device__ __forceinline__ void cp16z(uint32_t dst, const void* src, int srcsz) {
    asm volatile("cp.async.cg.shared.global [%0], [%1], 16, %2;"
                 :: "r"(dst), "l"(src), "r"(srcsz));
}
__device__ __forceinline__ void cp_commit() { asm volatile("cp.async.commit_group;"); }
template <int N>
__device__ __forceinline__ void cp_wait() {
    asm volatile("cp.async.wait_group %0;" :: "n"(N));
}

// ---------------------------------------------------------------------------
// Weight transforms. g_wt rows are 16B-chunk swizzled: for rows with
// (co>>2)&1 == 1, the half-index is XORed with 8 (16 bytes).
// ---------------------------------------------------------------------------
__global__ void wt_transform(const float* __restrict__ w_hid) {
    int idx = blockIdx.x * 256 + threadIdx.x;
    if (idx >= 7 * 25 * 128 * CP) return;
    int ci_out = idx % CP;
    int co = (idx / CP) % 128;
    int tap = (idx / (CP * 128)) % 25;
    int l = idx / (CP * 128 * 25);
    int ci = ((co >> 2) & 1) ? (ci_out ^ 8) : ci_out;
    float v = 0.f;
    if (co < F && ci < F)
        v = w_hid[(((size_t)l * F + co) * F + ci) * 25 + tap];
    g_wt[idx] = __float2half(v);
}

__global__ void wkp_transform(const float* __restrict__ w_kp) {
    int idx = blockIdx.x * 256 + threadIdx.x;
    if (idx >= KKP * CP) return;
    int ci = idx % CP;
    int co = idx / CP;
    float v = 0.f;
    if (co < KK && ci < F) v = w_kp[(size_t)co * F + ci];
    g_wkp[idx] = __float2half(v);
}

// ---------------------------------------------------------------------------
// Input conv 5x5 (3->100) + relu, fp32 FFMA, output fp16 NHWC[112].
// ---------------------------------------------------------------------------
__global__ __launch_bounds__(256)
void conv_in(const float* __restrict__ in, const float* __restrict__ w,
             const float* __restrict__ bias, __half* __restrict__ out) {
    __shared__ float s_in[3][36][37];
    __shared__ float s_w[3][25][10];

    const int t = threadIdx.x;
    const int tx = t & 15, ty = t >> 4;
    const int tileX = (blockIdx.x % 6) * 32;
    const int tileY = (blockIdx.x / 6) * 32;
    const int co0 = blockIdx.y * 10;
    const int b = blockIdx.z;
    const float* inb = in + (size_t)b * 3 * (HW * HW);

    for (int i = t; i < 3 * 36 * 36; i += 256) {
        int cc = i / (36 * 36);
        int rem = i - cc * (36 * 36);
        int r = rem / 36, c = rem - r * 36;
        int gy = tileY + r - 2, gx = tileX + c - 2;
        float v = 0.f;
        if ((unsigned)gy < HW && (unsigned)gx < HW)
            v = inb[(size_t)cc * (HW * HW) + gy * HW + gx];
        s_in[cc][r][c] = v;
    }
    for (int i = t; i < 3 * 250; i += 256) {
        int co = i % 10;
        int tap = (i / 10) % 25;
        int cc = i / 250;
        s_w[cc][tap][co] = w[((size_t)(co0 + co) * 3 + cc) * 25 + tap];
    }
    __syncthreads();

    float acc[10][4];
#pragma unroll
    for (int c = 0; c < 10; c++)
#pragma unroll
        for (int p = 0; p < 4; p++) acc[c][p] = 0.f;

#pragma unroll
    for (int cc = 0; cc < 3; cc++) {
#pragma unroll 1
        for (int ky = 0; ky < 5; ky++) {
            const int r0 = 2 * ty + ky;
#pragma unroll
            for (int kx = 0; kx < 5; kx++) {
                const int c0 = 2 * tx + kx;
                float x00 = s_in[cc][r0][c0];
                float x01 = s_in[cc][r0][c0 + 1];
                float x10 = s_in[cc][r0 + 1][c0];
                float x11 = s_in[cc][r0 + 1][c0 + 1];
                const int tap = ky * 5 + kx;
#pragma unroll
                for (int co = 0; co < 10; co++) {
                    float wv = s_w[cc][tap][co];
                    acc[co][0] = fmaf(wv, x00, acc[co][0]);
                    acc[co][1] = fmaf(wv, x01, acc[co][1]);
                    acc[co][2] = fmaf(wv, x10, acc[co][2]);
                    acc[co][3] = fmaf(wv, x11, acc[co][3]);
                }
            }
        }
    }

#pragma unroll
    for (int co = 0; co < 10; co++) {
        float bb = bias[co0 + co];
#pragma unroll
        for (int p = 0; p < 4; p++) {
            int ly = 2 * ty + (p >> 1);
            int lx = 2 * tx + (p & 1);
            float v = acc[co][p] + bb;
            v = v > 0.f ? v : 0.f;
            out[((size_t)(b * HW + tileY + ly) * HW + tileX + lx) * CP + co0 + co] =
                __float2half(v);
        }
    }
}

// ---------------------------------------------------------------------------
// Hidden conv 5x5 (100->100) + relu, fp16 tensor cores. (Round-9, unchanged.)
// ---------------------------------------------------------------------------
__global__ __launch_bounds__(256, 2)
void conv_hidden(const __half* __restrict__ act_in, const __half* __restrict__ wt,
                 const float* __restrict__ bias, __half* __restrict__ act_out) {
    extern __shared__ __align__(128) __half smem[];
    __half* s_patch = smem;                     // 240 pixel slots * PP halves = 53760 B
    __half* s_A = smem + 240 * PP;              // 2 buffers * 128 * PP = 57344 B
    const uint32_t A_BYTES = 128 * PP * 2;      // 28672

    const int t = threadIdx.x;
    const int lane = t & 31, w = t >> 5;
    const int mw = w & 3, nw = w >> 2;
    const int g = lane >> 2, tg = lane & 3;
    const int tileX = (blockIdx.x % 12) * 16;
    const int tileY = (blockIdx.x / 12) * 8;
    const int b = blockIdx.z;
    const int co0 = mw * 32;

    const uint32_t sp = smem_u32(s_patch);
    const uint32_t sA0 = smem_u32(s_A);

    {
        const __half* actb = act_in + (size_t)b * HW * HW * CP;
        for (int i = t; i < 240 * 14; i += 256) {
            int pix = i / 14, j = i % 14;
            int r = pix / 20, c = pix % 20;
            int gy = tileY + r - 2, gx = tileX + c - 2;
            bool ok = (unsigned)gy < HW && (unsigned)gx < HW;
            const char* src = ok
                ? (const char*)&actb[((size_t)gy * HW + gx) * CP] + j * 16
                : (const char*)actb;
            uint32_t dst = sp + (uint32_t)pix * (PP * 2) +
                           ((uint32_t)(j * 16) ^ (((pix >> 2) & 1) << 4));
            cp16z(dst, src, ok ? 16 : 0);
        }
    }
    {
        const char* wsrc = (const char*)wt;
        for (int i = t; i < 1792; i += 256)
            cp16(sA0 + (uint32_t)i * 16, wsrc + (size_t)i * 16);
    }
    cp_commit();

    uint32_t a_base[2];
#pragma unroll
    for (int mi = 0; mi < 2; mi++) {
        int row = co0 + mi * 16 + (lane & 15);
        uint32_t acol2 = (uint32_t)(lane >> 4) * 16;
        a_base[mi] = sA0 + (uint32_t)row * (PP * 2) +
                     (acol2 ^ (((uint32_t)(row >> 2) & 1) << 4));
    }

    uint32_t b_base[4];
    uint32_t s0pack = 0;
    {
        int sub = lane >> 3, pix = lane & 7;
#pragma unroll
        for (int j = 0; j < 4; j++) {
            int ni = 2 * j + (sub >> 1);
            int khalf = sub & 1;
            int pr0 = nw * 4 + (ni >> 1);
            int pc0 = (ni & 1) * 8 + pix;
            int s0 = pr0 * 20 + pc0;
            b_base[j] = sp + (uint32_t)s0 * (PP * 2) + (uint32_t)khalf * 16;
            s0pack |= (uint32_t)s0 << (8 * j);
        }
    }

    float acc[2][8][4];
#pragma unroll
    for (int mi = 0; mi < 2; mi++)
#pragma unroll
        for (int ni = 0; ni < 8; ni++)
#pragma unroll
            for (int p = 0; p < 4; p++) acc[mi][ni][p] = 0.f;

    cp_wait<0>();
    __syncthreads();

#pragma unroll 1
    for (int tap = 0; tap < 25; tap++) {
        if (tap < 24) {
            const char* wsrc = (const char*)(wt + (size_t)(tap + 1) * 128 * CP);
            uint32_t dst = sA0 + ((tap + 1) & 1) * A_BYTES;
            for (int i = t; i < 1792; i += 256)
                cp16(dst + (uint32_t)i * 16, wsrc + (size_t)i * 16);
            cp_commit();
        }

        const uint32_t aoff = (tap & 1) * A_BYTES;
        const int ky = tap / 5, kx = tap % 5;
        const int ds = ky * 20 + kx;
        const uint32_t dsb = (uint32_t)ds * (PP * 2);

        uint32_t b_tap[4];
#pragma unroll
        for (int j = 0; j < 4; j++) {
            uint32_t s0j = (s0pack >> (8 * j)) & 255u;
            uint32_t swz = ((s0j + (uint32_t)ds) << 2) & 16u;
            b_tap[j] = (b_base[j] + dsb) ^ swz;
        }

#pragma unroll
        for (int kc = 0; kc < CP; kc += 16) {
            uint32_t a[2][4];
#pragma unroll
            for (int mi = 0; mi < 2; mi++) ldm_x4(a[mi], a_base[mi] + aoff + kc * 2);
            uint32_t bf[8][2];
#pragma unroll
            for (int j = 0; j < 4; j++) {
                uint32_t r[4];
                ldm_x4(r, b_tap[j] + kc * 2);
                bf[2 * j][0] = r[0]; bf[2 * j][1] = r[1];
                bf[2 * j + 1][0] = r[2]; bf[2 * j + 1][1] = r[3];
            }
#pragma unroll
            for (int mi = 0; mi < 2; mi++)
#pragma unroll
                for (int ni = 0; ni < 8; ni++)
                    mma16816(acc[mi][ni], a[mi], bf[ni]);
        }

        if (tap < 24) {
            cp_wait<0>();
            __syncthreads();
        }
    }

#pragma unroll
    for (int mi = 0; mi < 2; mi++) {
        int co_a = co0 + mi * 16 + g;
        int co_b = co_a + 8;
        float ba = (co_a < F) ? bias[co_a] : 0.f;
        float bb = (co_b < F) ? bias[co_b] : 0.f;
#pragma unroll
        for (int ni = 0; ni < 8; ni++) {
            int py = tileY + nw * 4 + (ni >> 1);
            int px = tileX + ((ni & 1) << 3) + 2 * tg;
            size_t base = ((size_t)(b * HW + py) * HW + px) * CP;
            if (co_a < F) {
                float v0 = acc[mi][ni][0] + ba; v0 = v0 > 0.f ? v0 : 0.f;
                float v1 = acc[mi][ni][1] + ba; v1 = v1 > 0.f ? v1 : 0.f;
                act_out[base + co_a] = __float2half(v0);
                act_out[base + CP + co_a] = __float2half(v1);
            }
            if (co_b < F) {
                float v2 = acc[mi][ni][2] + bb; v2 = v2 > 0.f ? v2 : 0.f;
                float v3 = acc[mi][ni][3] + bb; v3 = v3 > 0.f ? v3 : 0.f;
                act_out[base + co_b] = __float2half(v2);
                act_out[base + CP + co_b] = __float2half(v3);
            }
        }
    }
}

// ---------------------------------------------------------------------------
// Fused kp: per CTA, 64 pixels (16x4 tile). Loop 4 chunks of 128 wkp rows:
// mma.sync GEMM (K=112) -> logits in smem transposed [co][pix] (pitch 66 ->
// apply reads are bank-conflict-free). Then softmax + 21x21 apply from smem.
// ---------------------------------------------------------------------------
// smem: s_px 64*120*2=15360; s_A 128*120*2=30720; s_lg 448*66*2=59136;
// s_patch 3*24*36*4=10368. total 115584.
#define SMEM_KP2 (15360 + 30720 + 59136 + 10368)

__global__ __launch_bounds__(256, 1)
void kp_fused2(const __half* __restrict__ feat, const float* __restrict__ noisy,
               const __half* __restrict__ wkp, const float* __restrict__ b_kp,
               float* __restrict__ out) {
    extern __shared__ __align__(128) char smc[];
    __half* s_px = (__half*)smc;                            // [64][120]
    __half* s_A = (__half*)(smc + 15360);                   // [128][120]
    __half* s_lg = (__half*)(smc + 15360 + 30720);          // [448][66]
    float* s_patch = (float*)(smc + 15360 + 30720 + 59136); // [3][24][36]

    const int t = threadIdx.x;
    const int lane = t & 31, w = t >> 5;
    const int mw = w & 3, nw = w >> 2;
    const int g = lane >> 2, tg = lane & 3;
    const int tileX = (blockIdx.x % 12) * 16;
    const int tileY = (blockIdx.x / 12) * 4;
    const int b = blockIdx.z;

    // Stage 64 pixels x 112 ch.
    {
        const __half* fb = feat + (size_t)b * HW * HW * CP;
        for (int i = t; i < 64 * 14; i += 256) {
            int pix = i / 14, j = i % 14;
            int gy = tileY + (pix >> 4), gx = tileX + (pix & 15);
            ((uint4*)&s_px[pix * PITCH])[j] =
                ((const uint4*)&fb[((size_t)gy * HW + gx) * CP])[j];
        }
    }
    // Stage noisy patch: 3ch x 24x36 (covers all 64 pixels' 21x21 windows).
    for (int i = t; i < 3 * 24 * 36; i += 256) {
        int c = i / (24 * 36);
        int rem = i - c * (24 * 36);
        int dy = rem / 36, dx = rem - dy * 36;
        int gy = tileY + dy - 10, gx = tileX + dx - 10;
        float v = 0.f;
        if ((unsigned)gy < HW && (unsigned)gx < HW)
            v = noisy[(((size_t)b * 3 + c) * HW + gy) * HW + gx];
        s_patch[(c * 24 + dy) * 36 + dx] = v;
    }

    uint32_t a_base[2];
#pragma unroll
    for (int mi = 0; mi < 2; mi++)
        a_base[mi] = smem_u32(&s_A[(mw * 32 + mi * 16 + (lane & 15)) * PITCH +
                                   (lane >> 4) * 8]);
    uint32_t b_base[2];
    {
        int sub = lane >> 3, pix8 = lane & 7;
#pragma unroll
        for (int j = 0; j < 2; j++) {
            int ni = 2 * j + (sub >> 1);
            int khalf = sub & 1;
            int pidx = nw * 32 + ni * 8 + pix8;
            b_base[j] = smem_u32(&s_px[pidx * PITCH + khalf * 8]);
        }
    }

#pragma unroll 1
    for (int cg = 0; cg < 4; cg++) {
        __syncthreads();   // staging done (cg=0) / prior chunk's s_A reads done
        for (int i = t; i < 128 * 14; i += 256) {
            int co = i / 14, j = i % 14;
            ((uint4*)&s_A[co * PITCH])[j] =
                ((const uint4*)&wkp[(size_t)(cg * 128 + co) * CP])[j];
        }
        __syncthreads();

        float acc[2][4][4];
#pragma unroll
        for (int mi = 0; mi < 2; mi++)
#pragma unroll
            for (int ni = 0; ni < 4; ni++)
#pragma unroll
                for (int p = 0; p < 4; p++) acc[mi][ni][p] = 0.f;

#pragma unroll
        for (int kc = 0; kc < CP; kc += 16) {
            uint32_t a[2][4];
#pragma unroll
            for (int mi = 0; mi < 2; mi++) ldm_x4(a[mi], a_base[mi] + kc * 2);
            uint32_t bf[4][2];
#pragma unroll
            for (int j = 0; j < 2; j++) {
                uint32_t r[4];
                ldm_x4(r, b_base[j] + kc * 2);
                bf[2 * j][0] = r[0]; bf[2 * j][1] = r[1];
                bf[2 * j + 1][0] = r[2]; bf[2 * j + 1][1] = r[3];
            }
#pragma unroll
            for (int mi = 0; mi < 2; mi++)
#pragma unroll
                for (int ni = 0; ni < 4; ni++)
                    mma16816(acc[mi][ni], a[mi], bf[ni]);
        }

        // Epilogue: bias + store fp16 logits transposed [co][pix].
#pragma unroll
        for (int mi = 0; mi < 2; mi++) {
            int co_a = cg * 128 + mw * 32 + mi * 16 + g;
            int co_b = co_a + 8;
            float ba = (co_a < KK) ? b_kp[co_a] : 0.f;
            float bb = (co_b < KK) ? b_kp[co_b] : 0.f;
#pragma unroll
            for (int ni = 0; ni < 4; ni++) {
                int pidx = nw * 32 + ni * 8 + 2 * tg;
                if (co_a < KK) {
                    __half2 h = __floats2half2_rn(acc[mi][ni][0] + ba,
                                                  acc[mi][ni][1] + ba);
                    *(__half2*)&s_lg[co_a * LGP + pidx] = h;
                }
                if (co_b < KK) {
                    __half2 h = __floats2half2_rn(acc[mi][ni][2] + bb,
                                                  acc[mi][ni][3] + bb);
                    *(__half2*)&s_lg[co_b * LGP + pidx] = h;
                }
            }
        }
    }
    __syncthreads();

    // Apply: warp per pixel, 8 passes.
#pragma unroll 1
    for (int it = 0; it < 8; it++) {
        int pidx = it * 8 + w;
        int py = pidx >> 4, pxl = pidx & 15;

        float L[14];
#pragma unroll
        for (int i = 0; i < 14; i++) {
            int j = i * 32 + lane;
            L[i] = (j < KK) ? __half2float(s_lg[j * LGP + pidx]) : -1e30f;
        }
        float m = -1e30f;
#pragma unroll
        for (int i = 0; i < 14; i++) m = fmaxf(m, L[i]);
#pragma unroll
        for (int o = 16; o; o >>= 1) m = fmaxf(m, __shfl_xor_sync(0xffffffffu, m, o));

        float se = 0.f, o0 = 0.f, o1 = 0.f, o2 = 0.f;
#pragma unroll
        for (int i = 0; i < 14; i++) {
            int j = i * 32 + lane;
            if (j < KK) {
                float e = __expf(L[i] - m);
                int ky = j / 21, kx = j - ky * 21;
                se += e;
                o0 += e * s_patch[(0 * 24 + py + ky) * 36 + pxl + kx];
                o1 += e * s_patch[(1 * 24 + py + ky) * 36 + pxl + kx];
                o2 += e * s_patch[(2 * 24 + py + ky) * 36 + pxl + kx];
            }
        }
#pragma unroll
        for (int o = 16; o; o >>= 1) {
            se += __shfl_xor_sync(0xffffffffu, se, o);
            o0 += __shfl_xor_sync(0xffffffffu, o0, o);
            o1 += __shfl_xor_sync(0xffffffffu, o1, o);
            o2 += __shfl_xor_sync(0xffffffffu, o2, o);
        }
        if (lane == 0) {
            float inv = 1.f / se;
            int y = tileY + py, x = tileX + pxl;
            out[(((size_t)b * 3 + 0) * HW + y) * HW + x] = o0 * inv;
            out[(((size_t)b * 3 + 1) * HW + y) * HW + x] = o1 * inv;
            out[(((size_t)b * 3 + 2) * HW + y) * HW + x] = o2 * inv;
        }
    }
}

// ---------------------------------------------------------------------------
extern "C" void kernel_launch(void* const* d_in, const int* in_sizes, int n_in,
                              void* d_out, int out_size) {
    const float* noisy = (const float*)d_in[0];
    const float* w_in  = (const float*)d_in[1];
    const float* b_in  = (const float*)d_in[2];
    const float* w_hid = (const float*)d_in[3];
    const float* b_hid = (const float*)d_in[4];
    const float* w_kp  = (const float*)d_in[5];
    const float* b_kp  = (const float*)d_in[6];
    float* out = (float*)d_out;

    __half *act0, *act1, *wt, *wkp;
    cudaGetSymbolAddress((void**)&act0, g_act0);
    cudaGetSymbolAddress((void**)&act1, g_act1);
    cudaGetSymbolAddress((void**)&wt, g_wt);
    cudaGetSymbolAddress((void**)&wkp, g_wkp);

    const int smem_hidden = 240 * PP * 2 + 2 * 128 * PP * 2;  // 111104 B
    cudaFuncSetAttribute(conv_hidden, cudaFuncAttributeMaxDynamicSharedMemorySize,
                         smem_hidden);
    cudaFuncSetAttribute(kp_fused2, cudaFuncAttributeMaxDynamicSharedMemorySize,
                         SMEM_KP2);

    const size_t actBytes = (size_t)2 * HW * HW * CP * sizeof(__half);
    cudaMemsetAsync(act0, 0, actBytes);
    cudaMemsetAsync(act1, 0, actBytes);

    wt_transform<<<(7 * 25 * 128 * CP + 255) / 256, 256>>>(w_hid);
    wkp_transform<<<(KKP * CP + 255) / 256, 256>>>(w_kp);

    conv_in<<<dim3(36, 10, 2), 256>>>(noisy, w_in, b_in, act0);

    const __half* src = act0;
    __half* dst = act1;
    for (int l = 0; l < 7; l++) {
        conv_hidden<<<dim3(288, 1, 2), 256, smem_hidden>>>(
            src, wt + (size_t)l * 25 * 128 * CP, b_hid + l * F, dst);
        __half* tmp = (__half*)src;
        src = dst;
        dst = tmp;
    }

    kp_fused2<<<dim3(576, 1, 2), 256, SMEM_KP2>>>(src, noisy, wkp, b_kp, out);
}

// round 12
// speedup vs baseline: 1.4403x; 1.0661x over previous
#include <cuda_runtime.h>
#include <cuda_fp16.h>
#include <cstdint>

#define HW 192
#define F 100
#define CP 112            // padded channel count (stored)
#define PP 112            // conv_hidden smem pitch in halves (224B; XOR-swizzled -> conflict-free)
#define PITCH 120         // kp smem pitch (conflict-free)
#define KK 441
#define KKP 448
#define LGP 66            // logits smem pitch in halves (132B -> lane-conflict-free reads)

// Activation ping-pong buffers: fp16 NHWC[112]: 2*192*192*112 halves = 16.5 MB each.
__device__ __half g_act0[2 * HW * HW * CP];
__device__ __half g_act1[2 * HW * HW * CP];
// Transformed hidden weights: [layer7][tap25][co128][ci112] fp16, 16B-chunk swizzled.
__device__ __half g_wt[7 * 25 * 128 * CP];
// Transformed kp weights: [448][112] fp16.
__device__ __half g_wkp[KKP * CP];

// ---------------------------------------------------------------------------
// PTX helpers
// ---------------------------------------------------------------------------
__device__ __forceinline__ uint32_t smem_u32(const void* p) {
    return (uint32_t)__cvta_generic_to_shared(p);
}
__device__ __forceinline__ void ldm_x4(uint32_t* r, uint32_t addr) {
    asm volatile("ldmatrix.sync.aligned.m8n8.x4.shared.b16 {%0,%1,%2,%3}, [%4];"
                 : "=r"(r[0]), "=r"(r[1]), "=r"(r[2]), "=r"(r[3]) : "r"(addr));
}
__device__ __forceinline__ void mma16816(float* c, const uint32_t* a, const uint32_t* b) {
    asm volatile(
        "mma.sync.aligned.m16n8k16.row.col.f32.f16.f16.f32 "
        "{%0,%1,%2,%3}, {%4,%5,%6,%7}, {%8,%9}, {%0,%1,%2,%3};"
        : "+f"(c[0]), "+f"(c[1]), "+f"(c[2]), "+f"(c[3])
        : "r"(a[0]), "r"(a[1]), "r"(a[2]), "r"(a[3]), "r"(b[0]), "r"(b[1]));
}
__device__ __forceinline__ void cp16(uint32_t dst, const void* src) {
    asm volatile("cp.async.cg.shared.global [%0], [%1], 16;" :: "r"(dst), "l"(src));
}
__device__ __forceinline__ void cp16z(uint32_t dst, const void* src, int srcsz) {
    asm volatile("cp.async.cg.shared.global [%0], [%1], 16, %2;"
                 :: "r"(dst), "l"(src), "r"(srcsz));
}
__device__ __forceinline__ void cp_commit() { asm volatile("cp.async.commit_group;"); }
template <int N>
__device__ __forceinline__ void cp_wait() {
    asm volatile("cp.async.wait_group %0;" :: "n"(N));
}

// ---------------------------------------------------------------------------
// Weight transforms. g_wt rows are 16B-chunk swizzled: for rows with
// (co>>2)&1 == 1, the half-index is XORed with 8 (16 bytes).
// ---------------------------------------------------------------------------
__global__ void wt_transform(const float* __restrict__ w_hid) {
    int idx = blockIdx.x * 256 + threadIdx.x;
    if (idx >= 7 * 25 * 128 * CP) return;
    int ci_out = idx % CP;
    int co = (idx / CP) % 128;
    int tap = (idx / (CP * 128)) % 25;
    int l = idx / (CP * 128 * 25);
    int ci = ((co >> 2) & 1) ? (ci_out ^ 8) : ci_out;
    float v = 0.f;
    if (co < F && ci < F)
        v = w_hid[(((size_t)l * F + co) * F + ci) * 25 + tap];
    g_wt[idx] = __float2half(v);
}

__global__ void wkp_transform(const float* __restrict__ w_kp) {
    int idx = blockIdx.x * 256 + threadIdx.x;
    if (idx >= KKP * CP) return;
    int ci = idx % CP;
    int co = idx / CP;
    float v = 0.f;
    if (co < KK && ci < F) v = w_kp[(size_t)co * F + ci];
    g_wkp[idx] = __float2half(v);
}

// ---------------------------------------------------------------------------
// Input conv 5x5 (3->100) + relu, fp32 FFMA, output fp16 NHWC[112].
// ---------------------------------------------------------------------------
__global__ __launch_bounds__(256)
void conv_in(const float* __restrict__ in, const float* __restrict__ w,
             const float* __restrict__ bias, __half* __restrict__ out) {
    __shared__ float s_in[3][36][37];
    __shared__ float s_w[3][25][10];

    const int t = threadIdx.x;
    const int tx = t & 15, ty = t >> 4;
    const int tileX = (blockIdx.x % 6) * 32;
    const int tileY = (blockIdx.x / 6) * 32;
    const int co0 = blockIdx.y * 10;
    const int b = blockIdx.z;
    const float* inb = in + (size_t)b * 3 * (HW * HW);

    for (int i = t; i < 3 * 36 * 36; i += 256) {
        int cc = i / (36 * 36);
        int rem = i - cc * (36 * 36);
        int r = rem / 36, c = rem - r * 36;
        int gy = tileY + r - 2, gx = tileX + c - 2;
        float v = 0.f;
        if ((unsigned)gy < HW && (unsigned)gx < HW)
            v = inb[(size_t)cc * (HW * HW) + gy * HW + gx];
        s_in[cc][r][c] = v;
    }
    for (int i = t; i < 3 * 250; i += 256) {
        int co = i % 10;
        int tap = (i / 10) % 25;
        int cc = i / 250;
        s_w[cc][tap][co] = w[((size_t)(co0 + co) * 3 + cc) * 25 + tap];
    }
    __syncthreads();

    float acc[10][4];
#pragma unroll
    for (int c = 0; c < 10; c++)
#pragma unroll
        for (int p = 0; p < 4; p++) acc[c][p] = 0.f;

#pragma unroll
    for (int cc = 0; cc < 3; cc++) {
#pragma unroll 1
        for (int ky = 0; ky < 5; ky++) {
            const int r0 = 2 * ty + ky;
#pragma unroll
            for (int kx = 0; kx < 5; kx++) {
                const int c0 = 2 * tx + kx;
                float x00 = s_in[cc][r0][c0];
                float x01 = s_in[cc][r0][c0 + 1];
                float x10 = s_in[cc][r0 + 1][c0];
                float x11 = s_in[cc][r0 + 1][c0 + 1];
                const int tap = ky * 5 + kx;
#pragma unroll
                for (int co = 0; co < 10; co++) {
                    float wv = s_w[cc][tap][co];
                    acc[co][0] = fmaf(wv, x00, acc[co][0]);
                    acc[co][1] = fmaf(wv, x01, acc[co][1]);
                    acc[co][2] = fmaf(wv, x10, acc[co][2]);
                    acc[co][3] = fmaf(wv, x11, acc[co][3]);
                }
            }
        }
    }

#pragma unroll
    for (int co = 0; co < 10; co++) {
        float bb = bias[co0 + co];
#pragma unroll
        for (int p = 0; p < 4; p++) {
            int ly = 2 * ty + (p >> 1);
            int lx = 2 * tx + (p & 1);
            float v = acc[co][p] + bb;
            v = v > 0.f ? v : 0.f;
            out[((size_t)(b * HW + tileY + ly) * HW + tileX + lx) * CP + co0 + co] =
                __float2half(v);
        }
    }
}

// ---------------------------------------------------------------------------
// Hidden conv 5x5 (100->100) + relu, fp16 tensor cores.
// CTA: 256 thr = 8 warps as 2M x 4N. Tile: 112 couts x 128 pixels (16w x 8h).
// mw=0 warps: co 0..63 (4 m16 strips); mw=1 warps: co 64..111 (3 strips).
// nw = w&3 is the SMSP index -> each SMSP holds one mw=0 + one mw=1 warp
// (balanced 28 MMA/K-step/SMSP/CTA). A double-buffered via cp.async.
// ---------------------------------------------------------------------------
__global__ __launch_bounds__(256, 2)
void conv_hidden(const __half* __restrict__ act_in, const __half* __restrict__ wt,
                 const float* __restrict__ bias, __half* __restrict__ act_out) {
    extern __shared__ __align__(128) __half smem[];
    __half* s_patch = smem;                     // 240 pixel slots * PP halves = 53760 B
    __half* s_A = smem + 240 * PP;              // 2 buffers * 112 * PP = 50176 B
    const uint32_t A_BYTES = 112 * PP * 2;      // 25088

    const int t = threadIdx.x;
    const int lane = t & 31, w = t >> 5;
    const int nw = w & 3, mw = w >> 2;          // 4 N x 2 M
    const int g = lane >> 2, tg = lane & 3;
    const int tileX = (blockIdx.x % 12) * 16;
    const int tileY = (blockIdx.x / 12) * 8;
    const int b = blockIdx.z;
    const int co0 = mw * 64;
    const int nmi = mw ? 3 : 4;                 // m16 strips this warp owns

    const uint32_t sp = smem_u32(s_patch);
    const uint32_t sA0 = smem_u32(s_A);

    // Stage input patch (12x20 pixels x 112 ch), XOR-16B swizzled.
    {
        const __half* actb = act_in + (size_t)b * HW * HW * CP;
        for (int i = t; i < 240 * 14; i += 256) {
            int pix = i / 14, j = i % 14;
            int r = pix / 20, c = pix % 20;
            int gy = tileY + r - 2, gx = tileX + c - 2;
            bool ok = (unsigned)gy < HW && (unsigned)gx < HW;
            const char* src = ok
                ? (const char*)&actb[((size_t)gy * HW + gx) * CP] + j * 16
                : (const char*)actb;
            uint32_t dst = sp + (uint32_t)pix * (PP * 2) +
                           ((uint32_t)(j * 16) ^ (((pix >> 2) & 1) << 4));
            cp16z(dst, src, ok ? 16 : 0);
        }
    }
    // Stage A tap 0 (first 112 of 128 weight rows; rest are zero-pad, unused).
    {
        const char* wsrc = (const char*)wt;
        for (int i = t; i < 1568; i += 256)
            cp16(sA0 + (uint32_t)i * 16, wsrc + (size_t)i * 16);
    }
    cp_commit();

    uint32_t a_base[4];
#pragma unroll
    for (int mi = 0; mi < 4; mi++) {
        int row = co0 + mi * 16 + (lane & 15);
        if (row > 111) row = 111;               // unused for mw=1, keep in bounds
        uint32_t acol2 = (uint32_t)(lane >> 4) * 16;
        a_base[mi] = sA0 + (uint32_t)row * (PP * 2) +
                     (acol2 ^ (((uint32_t)(row >> 2) & 1) << 4));
    }

    uint32_t b_base[2];
    uint32_t s0pack = 0;
    {
        int sub = lane >> 3, pix = lane & 7;
#pragma unroll
        for (int j = 0; j < 2; j++) {
            int ni = 2 * j + (sub >> 1);
            int khalf = sub & 1;
            int pr0 = nw * 2 + (ni >> 1);
            int pc0 = (ni & 1) * 8 + pix;
            int s0 = pr0 * 20 + pc0;
            b_base[j] = sp + (uint32_t)s0 * (PP * 2) + (uint32_t)khalf * 16;
            s0pack |= (uint32_t)s0 << (8 * j);
        }
    }

    float acc[4][4][4];
#pragma unroll
    for (int mi = 0; mi < 4; mi++)
#pragma unroll
        for (int ni = 0; ni < 4; ni++)
#pragma unroll
            for (int p = 0; p < 4; p++) acc[mi][ni][p] = 0.f;

    cp_wait<0>();
    __syncthreads();

#pragma unroll 1
    for (int tap = 0; tap < 25; tap++) {
        if (tap < 24) {
            const char* wsrc = (const char*)(wt + (size_t)(tap + 1) * 128 * CP);
            uint32_t dst = sA0 + ((tap + 1) & 1) * A_BYTES;
            for (int i = t; i < 1568; i += 256)
                cp16(dst + (uint32_t)i * 16, wsrc + (size_t)i * 16);
            cp_commit();
        }

        const uint32_t aoff = (tap & 1) * A_BYTES;
        const int ky = tap / 5, kx = tap % 5;
        const int ds = ky * 20 + kx;
        const uint32_t dsb = (uint32_t)ds * (PP * 2);

        uint32_t b_tap[2];
#pragma unroll
        for (int j = 0; j < 2; j++) {
            uint32_t s0j = (s0pack >> (8 * j)) & 255u;
            uint32_t swz = ((s0j + (uint32_t)ds) << 2) & 16u;
            b_tap[j] = (b_base[j] + dsb) ^ swz;
        }

        if (mw == 0) {
#pragma unroll
            for (int kc = 0; kc < CP; kc += 16) {
                uint32_t a[4][4];
#pragma unroll
                for (int mi = 0; mi < 4; mi++) ldm_x4(a[mi], a_base[mi] + aoff + kc * 2);
                uint32_t bf[4][2];
#pragma unroll
                for (int j = 0; j < 2; j++) {
                    uint32_t r[4];
                    ldm_x4(r, b_tap[j] + kc * 2);
                    bf[2 * j][0] = r[0]; bf[2 * j][1] = r[1];
                    bf[2 * j + 1][0] = r[2]; bf[2 * j + 1][1] = r[3];
                }
#pragma unroll
                for (int mi = 0; mi < 4; mi++)
#pragma unroll
                    for (int ni = 0; ni < 4; ni++)
                        mma16816(acc[mi][ni], a[mi], bf[ni]);
            }
        } else {
#pragma unroll
            for (int kc = 0; kc < CP; kc += 16) {
                uint32_t a[3][4];
#pragma unroll
                for (int mi = 0; mi < 3; mi++) ldm_x4(a[mi], a_base[mi] + aoff + kc * 2);
                uint32_t bf[4][2];
#pragma unroll
                for (int j = 0; j < 2; j++) {
                    uint32_t r[4];
                    ldm_x4(r, b_tap[j] + kc * 2);
                    bf[2 * j][0] = r[0]; bf[2 * j][1] = r[1];
                    bf[2 * j + 1][0] = r[2]; bf[2 * j + 1][1] = r[3];
                }
#pragma unroll
                for (int mi = 0; mi < 3; mi++)
#pragma unroll
                    for (int ni = 0; ni < 4; ni++)
                        mma16816(acc[mi][ni], a[mi], bf[ni]);
            }
        }

        if (tap < 24) {
            cp_wait<0>();
            __syncthreads();
        }
    }

    // Writeback: bias + relu -> fp16 NHWC (co < 100 only; pad stays zero).
#pragma unroll
    for (int mi = 0; mi < 4; mi++) {
        if (mi >= nmi) break;
        int co_a = co0 + mi * 16 + g;
        int co_b = co_a + 8;
        float ba = (co_a < F) ? bias[co_a] : 0.f;
        float bb = (co_b < F) ? bias[co_b] : 0.f;
#pragma unroll
        for (int ni = 0; ni < 4; ni++) {
            int py = tileY + nw * 2 + (ni >> 1);
            int px = tileX + ((ni & 1) << 3) + 2 * tg;
            size_t base = ((size_t)(b * HW + py) * HW + px) * CP;
            if (co_a < F) {
                float v0 = acc[mi][ni][0] + ba; v0 = v0 > 0.f ? v0 : 0.f;
                float v1 = acc[mi][ni][1] + ba; v1 = v1 > 0.f ? v1 : 0.f;
                act_out[base + co_a] = __float2half(v0);
                act_out[base + CP + co_a] = __float2half(v1);
            }
            if (co_b < F) {
                float v2 = acc[mi][ni][2] + bb; v2 = v2 > 0.f ? v2 : 0.f;
                float v3 = acc[mi][ni][3] + bb; v3 = v3 > 0.f ? v3 : 0.f;
                act_out[base + co_b] = __float2half(v2);
                act_out[base + CP + co_b] = __float2half(v3);
            }
        }
    }
}

// ---------------------------------------------------------------------------
// Fused kp: per CTA, 64 pixels (16x4 tile). GEMM over 4 chunks of 128 wkp
// rows -> logits in smem transposed [co][pix], then softmax + apply in-place.
// ---------------------------------------------------------------------------
#define SMEM_KP2 (15360 + 30720 + 59136 + 10368)

__global__ __launch_bounds__(256, 1)
void kp_fused2(const __half* __restrict__ feat, const float* __restrict__ noisy,
               const __half* __restrict__ wkp, const float* __restrict__ b_kp,
               float* __restrict__ out) {
    extern __shared__ __align__(128) char smc[];
    __half* s_px = (__half*)smc;                            // [64][120]
    __half* s_A = (__half*)(smc + 15360);                   // [128][120]
    __half* s_lg = (__half*)(smc + 15360 + 30720);          // [448][66]
    float* s_patch = (float*)(smc + 15360 + 30720 + 59136); // [3][24][36]

    const int t = threadIdx.x;
    const int lane = t & 31, w = t >> 5;
    const int mw = w & 3, nw = w >> 2;
    const int g = lane >> 2, tg = lane & 3;
    const int tileX = (blockIdx.x % 12) * 16;
    const int tileY = (blockIdx.x / 12) * 4;
    const int b = blockIdx.z;

    {
        const __half* fb = feat + (size_t)b * HW * HW * CP;
        for (int i = t; i < 64 * 14; i += 256) {
            int pix = i / 14, j = i % 14;
            int gy = tileY + (pix >> 4), gx = tileX + (pix & 15);
            ((uint4*)&s_px[pix * PITCH])[j] =
                ((const uint4*)&fb[((size_t)gy * HW + gx) * CP])[j];
        }
    }
    for (int i = t; i < 3 * 24 * 36; i += 256) {
        int c = i / (24 * 36);
        int rem = i - c * (24 * 36);
        int dy = rem / 36, dx = rem - dy * 36;
        int gy = tileY + dy - 10, gx = tileX + dx - 10;
        float v = 0.f;
        if ((unsigned)gy < HW && (unsigned)gx < HW)
            v = noisy[(((size_t)b * 3 + c) * HW + gy) * HW + gx];
        s_patch[(c * 24 + dy) * 36 + dx] = v;
    }

    uint32_t a_base[2];
#pragma unroll
    for (int mi = 0; mi < 2; mi++)
        a_base[mi] = smem_u32(&s_A[(mw * 32 + mi * 16 + (lane & 15)) * PITCH +
                                   (lane >> 4) * 8]);
    uint32_t b_base[2];
    {
        int sub = lane >> 3, pix8 = lane & 7;
#pragma unroll
        for (int j = 0; j < 2; j++) {
            int ni = 2 * j + (sub >> 1);
            int khalf = sub & 1;
            int pidx = nw * 32 + ni * 8 + pix8;
            b_base[j] = smem_u32(&s_px[pidx * PITCH + khalf * 8]);
        }
    }

#pragma unroll 1
    for (int cg = 0; cg < 4; cg++) {
        __syncthreads();
        for (int i = t; i < 128 * 14; i += 256) {
            int co = i / 14, j = i % 14;
            ((uint4*)&s_A[co * PITCH])[j] =
                ((const uint4*)&wkp[(size_t)(cg * 128 + co) * CP])[j];
        }
        __syncthreads();

        float acc[2][4][4];
#pragma unroll
        for (int mi = 0; mi < 2; mi++)
#pragma unroll
            for (int ni = 0; ni < 4; ni++)
#pragma unroll
                for (int p = 0; p < 4; p++) acc[mi][ni][p] = 0.f;

#pragma unroll
        for (int kc = 0; kc < CP; kc += 16) {
            uint32_t a[2][4];
#pragma unroll
            for (int mi = 0; mi < 2; mi++) ldm_x4(a[mi], a_base[mi] + kc * 2);
            uint32_t bf[4][2];
#pragma unroll
            for (int j = 0; j < 2; j++) {
                uint32_t r[4];
                ldm_x4(r, b_base[j] + kc * 2);
                bf[2 * j][0] = r[0]; bf[2 * j][1] = r[1];
                bf[2 * j + 1][0] = r[2]; bf[2 * j + 1][1] = r[3];
            }
#pragma unroll
            for (int mi = 0; mi < 2; mi++)
#pragma unroll
                for (int ni = 0; ni < 4; ni++)
                    mma16816(acc[mi][ni], a[mi], bf[ni]);
        }

#pragma unroll
        for (int mi = 0; mi < 2; mi++) {
            int co_a = cg * 128 + mw * 32 + mi * 16 + g;
            int co_b = co_a + 8;
            float ba = (co_a < KK) ? b_kp[co_a] : 0.f;
            float bb = (co_b < KK) ? b_kp[co_b] : 0.f;
#pragma unroll
            for (int ni = 0; ni < 4; ni++) {
                int pidx = nw * 32 + ni * 8 + 2 * tg;
                if (co_a < KK) {
                    __half2 h = __floats2half2_rn(acc[mi][ni][0] + ba,
                                                  acc[mi][ni][1] + ba);
                    *(__half2*)&s_lg[co_a * LGP + pidx] = h;
                }
                if (co_b < KK) {
                    __half2 h = __floats2half2_rn(acc[mi][ni][2] + bb,
                                                  acc[mi][ni][3] + bb);
                    *(__half2*)&s_lg[co_b * LGP + pidx] = h;
                }
            }
        }
    }
    __syncthreads();

#pragma unroll 1
    for (int it = 0; it < 8; it++) {
        int pidx = it * 8 + w;
        int py = pidx >> 4, pxl = pidx & 15;

        float L[14];
#pragma unroll
        for (int i = 0; i < 14; i++) {
            int j = i * 32 + lane;
            L[i] = (j < KK) ? __half2float(s_lg[j * LGP + pidx]) : -1e30f;
        }
        float m = -1e30f;
#pragma unroll
        for (int i = 0; i < 14; i++) m = fmaxf(m, L[i]);
#pragma unroll
        for (int o = 16; o; o >>= 1) m = fmaxf(m, __shfl_xor_sync(0xffffffffu, m, o));

        float se = 0.f, o0 = 0.f, o1 = 0.f, o2 = 0.f;
#pragma unroll
        for (int i = 0; i < 14; i++) {
            int j = i * 32 + lane;
            if (j < KK) {
                float e = __expf(L[i] - m);
                int ky = j / 21, kx = j - ky * 21;
                se += e;
                o0 += e * s_patch[(0 * 24 + py + ky) * 36 + pxl + kx];
                o1 += e * s_patch[(1 * 24 + py + ky) * 36 + pxl + kx];
                o2 += e * s_patch[(2 * 24 + py + ky) * 36 + pxl + kx];
            }
        }
#pragma unroll
        for (int o = 16; o; o >>= 1) {
            se += __shfl_xor_sync(0xffffffffu, se, o);
            o0 += __shfl_xor_sync(0xffffffffu, o0, o);
            o1 += __shfl_xor_sync(0xffffffffu, o1, o);
            o2 += __shfl_xor_sync(0xffffffffu, o2, o);
        }
        if (lane == 0) {
            float inv = 1.f / se;
            int y = tileY + py, x = tileX + pxl;
            out[(((size_t)b * 3 + 0) * HW + y) * HW + x] = o0 * inv;
            out[(((size_t)b * 3 + 1) * HW + y) * HW + x] = o1 * inv;
            out[(((size_t)b * 3 + 2) * HW + y) * HW + x] = o2 * inv;
        }
    }
}

// ---------------------------------------------------------------------------
extern "C" void kernel_launch(void* const* d_in, const int* in_sizes, int n_in,
                              void* d_out, int out_size) {
    const float* noisy = (const float*)d_in[0];
    const float* w_in  = (const float*)d_in[1];
    const float* b_in  = (const float*)d_in[2];
    const float* w_hid = (const float*)d_in[3];
    const float* b_hid = (const float*)d_in[4];
    const float* w_kp  = (const float*)d_in[5];
    const float* b_kp  = (const float*)d_in[6];
    float* out = (float*)d_out;

    __half *act0, *act1, *wt, *wkp;
    cudaGetSymbolAddress((void**)&act0, g_act0);
    cudaGetSymbolAddress((void**)&act1, g_act1);
    cudaGetSymbolAddress((void**)&wt, g_wt);
    cudaGetSymbolAddress((void**)&wkp, g_wkp);

    const int smem_hidden = 240 * PP * 2 + 2 * 112 * PP * 2;  // 53760 + 50176 = 103936 B
    cudaFuncSetAttribute(conv_hidden, cudaFuncAttributeMaxDynamicSharedMemorySize,
                         smem_hidden);
    cudaFuncSetAttribute(kp_fused2, cudaFuncAttributeMaxDynamicSharedMemorySize,
                         SMEM_KP2);

    const size_t actBytes = (size_t)2 * HW * HW * CP * sizeof(__half);
    cudaMemsetAsync(act0, 0, actBytes);
    cudaMemsetAsync(act1, 0, actBytes);

    wt_transform<<<(7 * 25 * 128 * CP + 255) / 256, 256>>>(w_hid);
    wkp_transform<<<(KKP * CP + 255) / 256, 256>>>(w_kp);

    conv_in<<<dim3(36, 10, 2), 256>>>(noisy, w_in, b_in, act0);

    const __half* src = act0;
    __half* dst = act1;
    for (int l = 0; l < 7; l++) {
        conv_hidden<<<dim3(288, 1, 2), 256, smem_hidden>>>(
            src, wt + (size_t)l * 25 * 128 * CP, b_hid + l * F, dst);
        __half* tmp = (__half*)src;
        src = dst;
        dst = tmp;
    }

    kp_fused2<<<dim3(576, 1, 2), 256, SMEM_KP2>>>(src, noisy, wkp, b_kp, out);
}

// round 13
// speedup vs baseline: 1.4519x; 1.0081x over previous
#include <cuda_runtime.h>
#include <cuda_fp16.h>
#include <cstdint>

#define HW 192
#define F 100
#define CP 112            // padded channel count (stored)
#define PP 112            // conv_hidden smem pitch in halves (224B; XOR-swizzled -> conflict-free)
#define PITCH 120         // kp smem pitch (conflict-free)
#define KK 441
#define KKP 448
#define LGP 66            // logits smem pitch in halves (132B -> lane-conflict-free reads)

// Activation ping-pong buffers: fp16 NHWC[112]: 2*192*192*112 halves = 16.5 MB each.
// Pad channels 100..111 are never written by any kernel; they remain the
// zero-initialized value of __device__ globals (required by conv_hidden's K-MACs).
__device__ __half g_act0[2 * HW * HW * CP];
__device__ __half g_act1[2 * HW * HW * CP];
// Transformed hidden weights: [layer7][tap25][co128][ci112] fp16, 16B-chunk swizzled.
__device__ __half g_wt[7 * 25 * 128 * CP];
// Transformed kp weights: [448][112] fp16.
__device__ __half g_wkp[KKP * CP];

// ---------------------------------------------------------------------------
// PTX helpers
// ---------------------------------------------------------------------------
__device__ __forceinline__ uint32_t smem_u32(const void* p) {
    return (uint32_t)__cvta_generic_to_shared(p);
}
__device__ __forceinline__ void ldm_x4(uint32_t* r, uint32_t addr) {
    asm volatile("ldmatrix.sync.aligned.m8n8.x4.shared.b16 {%0,%1,%2,%3}, [%4];"
                 : "=r"(r[0]), "=r"(r[1]), "=r"(r[2]), "=r"(r[3]) : "r"(addr));
}
__device__ __forceinline__ void mma16816(float* c, const uint32_t* a, const uint32_t* b) {
    asm volatile(
        "mma.sync.aligned.m16n8k16.row.col.f32.f16.f16.f32 "
        "{%0,%1,%2,%3}, {%4,%5,%6,%7}, {%8,%9}, {%0,%1,%2,%3};"
        : "+f"(c[0]), "+f"(c[1]), "+f"(c[2]), "+f"(c[3])
        : "r"(a[0]), "r"(a[1]), "r"(a[2]), "r"(a[3]), "r"(b[0]), "r"(b[1]));
}
__device__ __forceinline__ void cp16(uint32_t dst, const void* src) {
    asm volatile("cp.async.cg.shared.global [%0], [%1], 16;" :: "r"(dst), "l"(src));
}
__device__ __forceinline__ void cp16z(uint32_t dst, const void* src, int srcsz) {
    asm volatile("cp.async.cg.shared.global [%0], [%1], 16, %2;"
                 :: "r"(dst), "l"(src), "r"(srcsz));
}
__device__ __forceinline__ void cp_commit() { asm volatile("cp.async.commit_group;"); }
template <int N>
__device__ __forceinline__ void cp_wait() {
    asm volatile("cp.async.wait_group %0;" :: "n"(N));
}

// ---------------------------------------------------------------------------
// Weight transforms. g_wt rows are 16B-chunk swizzled: for rows with
// (co>>2)&1 == 1, the half-index is XORed with 8 (16 bytes).
// ---------------------------------------------------------------------------
__global__ void wt_transform(const float* __restrict__ w_hid) {
    int idx = blockIdx.x * 256 + threadIdx.x;
    if (idx >= 7 * 25 * 128 * CP) return;
    int ci_out = idx % CP;
    int co = (idx / CP) % 128;
    int tap = (idx / (CP * 128)) % 25;
    int l = idx / (CP * 128 * 25);
    int ci = ((co >> 2) & 1) ? (ci_out ^ 8) : ci_out;
    float v = 0.f;
    if (co < F && ci < F)
        v = w_hid[(((size_t)l * F + co) * F + ci) * 25 + tap];
    g_wt[idx] = __float2half(v);
}

__global__ void wkp_transform(const float* __restrict__ w_kp) {
    int idx = blockIdx.x * 256 + threadIdx.x;
    if (idx >= KKP * CP) return;
    int ci = idx % CP;
    int co = idx / CP;
    float v = 0.f;
    if (co < KK && ci < F) v = w_kp[(size_t)co * F + ci];
    g_wkp[idx] = __float2half(v);
}

// ---------------------------------------------------------------------------
// Input conv 5x5 (3->100) + relu, fp32 FFMA, output fp16 NHWC[112].
// ---------------------------------------------------------------------------
__global__ __launch_bounds__(256)
void conv_in(const float* __restrict__ in, const float* __restrict__ w,
             const float* __restrict__ bias, __half* __restrict__ out) {
    __shared__ float s_in[3][36][37];
    __shared__ float s_w[3][25][10];

    const int t = threadIdx.x;
    const int tx = t & 15, ty = t >> 4;
    const int tileX = (blockIdx.x % 6) * 32;
    const int tileY = (blockIdx.x / 6) * 32;
    const int co0 = blockIdx.y * 10;
    const int b = blockIdx.z;
    const float* inb = in + (size_t)b * 3 * (HW * HW);

    for (int i = t; i < 3 * 36 * 36; i += 256) {
        int cc = i / (36 * 36);
        int rem = i - cc * (36 * 36);
        int r = rem / 36, c = rem - r * 36;
        int gy = tileY + r - 2, gx = tileX + c - 2;
        float v = 0.f;
        if ((unsigned)gy < HW && (unsigned)gx < HW)
            v = inb[(size_t)cc * (HW * HW) + gy * HW + gx];
        s_in[cc][r][c] = v;
    }
    for (int i = t; i < 3 * 250; i += 256) {
        int co = i % 10;
        int tap = (i / 10) % 25;
        int cc = i / 250;
        s_w[cc][tap][co] = w[((size_t)(co0 + co) * 3 + cc) * 25 + tap];
    }
    __syncthreads();

    float acc[10][4];
#pragma unroll
    for (int c = 0; c < 10; c++)
#pragma unroll
        for (int p = 0; p < 4; p++) acc[c][p] = 0.f;

#pragma unroll
    for (int cc = 0; cc < 3; cc++) {
#pragma unroll 1
        for (int ky = 0; ky < 5; ky++) {
            const int r0 = 2 * ty + ky;
#pragma unroll
            for (int kx = 0; kx < 5; kx++) {
                const int c0 = 2 * tx + kx;
                float x00 = s_in[cc][r0][c0];
                float x01 = s_in[cc][r0][c0 + 1];
                float x10 = s_in[cc][r0 + 1][c0];
                float x11 = s_in[cc][r0 + 1][c0 + 1];
                const int tap = ky * 5 + kx;
#pragma unroll
                for (int co = 0; co < 10; co++) {
                    float wv = s_w[cc][tap][co];
                    acc[co][0] = fmaf(wv, x00, acc[co][0]);
                    acc[co][1] = fmaf(wv, x01, acc[co][1]);
                    acc[co][2] = fmaf(wv, x10, acc[co][2]);
                    acc[co][3] = fmaf(wv, x11, acc[co][3]);
                }
            }
        }
    }

#pragma unroll
    for (int co = 0; co < 10; co++) {
        float bb = bias[co0 + co];
#pragma unroll
        for (int p = 0; p < 4; p++) {
            int ly = 2 * ty + (p >> 1);
            int lx = 2 * tx + (p & 1);
            float v = acc[co][p] + bb;
            v = v > 0.f ? v : 0.f;
            out[((size_t)(b * HW + tileY + ly) * HW + tileX + lx) * CP + co0 + co] =
                __float2half(v);
        }
    }
}

// ---------------------------------------------------------------------------
// Hidden conv 5x5 (100->100) + relu, fp16 tensor cores. (Round-12, unchanged.)
// CTA: 256 thr = 8 warps as 2M x 4N. Tile: 112 couts x 128 pixels (16w x 8h).
// ---------------------------------------------------------------------------
__global__ __launch_bounds__(256, 2)
void conv_hidden(const __half* __restrict__ act_in, const __half* __restrict__ wt,
                 const float* __restrict__ bias, __half* __restrict__ act_out) {
    extern __shared__ __align__(128) __half smem[];
    __half* s_patch = smem;                     // 240 pixel slots * PP halves = 53760 B
    __half* s_A = smem + 240 * PP;              // 2 buffers * 112 * PP = 50176 B
    const uint32_t A_BYTES = 112 * PP * 2;      // 25088

    const int t = threadIdx.x;
    const int lane = t & 31, w = t >> 5;
    const int nw = w & 3, mw = w >> 2;          // 4 N x 2 M
    const int g = lane >> 2, tg = lane & 3;
    const int tileX = (blockIdx.x % 12) * 16;
    const int tileY = (blockIdx.x / 12) * 8;
    const int b = blockIdx.z;
    const int co0 = mw * 64;
    const int nmi = mw ? 3 : 4;

    const uint32_t sp = smem_u32(s_patch);
    const uint32_t sA0 = smem_u32(s_A);

    {
        const __half* actb = act_in + (size_t)b * HW * HW * CP;
        for (int i = t; i < 240 * 14; i += 256) {
            int pix = i / 14, j = i % 14;
            int r = pix / 20, c = pix % 20;
            int gy = tileY + r - 2, gx = tileX + c - 2;
            bool ok = (unsigned)gy < HW && (unsigned)gx < HW;
            const char* src = ok
                ? (const char*)&actb[((size_t)gy * HW + gx) * CP] + j * 16
                : (const char*)actb;
            uint32_t dst = sp + (uint32_t)pix * (PP * 2) +
                           ((uint32_t)(j * 16) ^ (((pix >> 2) & 1) << 4));
            cp16z(dst, src, ok ? 16 : 0);
        }
    }
    {
        const char* wsrc = (const char*)wt;
        for (int i = t; i < 1568; i += 256)
            cp16(sA0 + (uint32_t)i * 16, wsrc + (size_t)i * 16);
    }
    cp_commit();

    uint32_t a_base[4];
#pragma unroll
    for (int mi = 0; mi < 4; mi++) {
        int row = co0 + mi * 16 + (lane & 15);
        if (row > 111) row = 111;
        uint32_t acol2 = (uint32_t)(lane >> 4) * 16;
        a_base[mi] = sA0 + (uint32_t)row * (PP * 2) +
                     (acol2 ^ (((uint32_t)(row >> 2) & 1) << 4));
    }

    uint32_t b_base[2];
    uint32_t s0pack = 0;
    {
        int sub = lane >> 3, pix = lane & 7;
#pragma unroll
        for (int j = 0; j < 2; j++) {
            int ni = 2 * j + (sub >> 1);
            int khalf = sub & 1;
            int pr0 = nw * 2 + (ni >> 1);
            int pc0 = (ni & 1) * 8 + pix;
            int s0 = pr0 * 20 + pc0;
            b_base[j] = sp + (uint32_t)s0 * (PP * 2) + (uint32_t)khalf * 16;
            s0pack |= (uint32_t)s0 << (8 * j);
        }
    }

    float acc[4][4][4];
#pragma unroll
    for (int mi = 0; mi < 4; mi++)
#pragma unroll
        for (int ni = 0; ni < 4; ni++)
#pragma unroll
            for (int p = 0; p < 4; p++) acc[mi][ni][p] = 0.f;

    cp_wait<0>();
    __syncthreads();

#pragma unroll 1
    for (int tap = 0; tap < 25; tap++) {
        if (tap < 24) {
            const char* wsrc = (const char*)(wt + (size_t)(tap + 1) * 128 * CP);
            uint32_t dst = sA0 + ((tap + 1) & 1) * A_BYTES;
            for (int i = t; i < 1568; i += 256)
                cp16(dst + (uint32_t)i * 16, wsrc + (size_t)i * 16);
            cp_commit();
        }

        const uint32_t aoff = (tap & 1) * A_BYTES;
        const int ky = tap / 5, kx = tap % 5;
        const int ds = ky * 20 + kx;
        const uint32_t dsb = (uint32_t)ds * (PP * 2);

        uint32_t b_tap[2];
#pragma unroll
        for (int j = 0; j < 2; j++) {
            uint32_t s0j = (s0pack >> (8 * j)) & 255u;
            uint32_t swz = ((s0j + (uint32_t)ds) << 2) & 16u;
            b_tap[j] = (b_base[j] + dsb) ^ swz;
        }

        if (mw == 0) {
#pragma unroll
            for (int kc = 0; kc < CP; kc += 16) {
                uint32_t a[4][4];
#pragma unroll
                for (int mi = 0; mi < 4; mi++) ldm_x4(a[mi], a_base[mi] + aoff + kc * 2);
                uint32_t bf[4][2];
#pragma unroll
                for (int j = 0; j < 2; j++) {
                    uint32_t r[4];
                    ldm_x4(r, b_tap[j] + kc * 2);
                    bf[2 * j][0] = r[0]; bf[2 * j][1] = r[1];
                    bf[2 * j + 1][0] = r[2]; bf[2 * j + 1][1] = r[3];
                }
#pragma unroll
                for (int mi = 0; mi < 4; mi++)
#pragma unroll
                    for (int ni = 0; ni < 4; ni++)
                        mma16816(acc[mi][ni], a[mi], bf[ni]);
            }
        } else {
#pragma unroll
            for (int kc = 0; kc < CP; kc += 16) {
                uint32_t a[3][4];
#pragma unroll
                for (int mi = 0; mi < 3; mi++) ldm_x4(a[mi], a_base[mi] + aoff + kc * 2);
                uint32_t bf[4][2];
#pragma unroll
                for (int j = 0; j < 2; j++) {
                    uint32_t r[4];
                    ldm_x4(r, b_tap[j] + kc * 2);
                    bf[2 * j][0] = r[0]; bf[2 * j][1] = r[1];
                    bf[2 * j + 1][0] = r[2]; bf[2 * j + 1][1] = r[3];
                }
#pragma unroll
                for (int mi = 0; mi < 3; mi++)
#pragma unroll
                    for (int ni = 0; ni < 4; ni++)
                        mma16816(acc[mi][ni], a[mi], bf[ni]);
            }
        }

        if (tap < 24) {
            cp_wait<0>();
            __syncthreads();
        }
    }

#pragma unroll
    for (int mi = 0; mi < 4; mi++) {
        if (mi >= nmi) break;
        int co_a = co0 + mi * 16 + g;
        int co_b = co_a + 8;
        float ba = (co_a < F) ? bias[co_a] : 0.f;
        float bb = (co_b < F) ? bias[co_b] : 0.f;
#pragma unroll
        for (int ni = 0; ni < 4; ni++) {
            int py = tileY + nw * 2 + (ni >> 1);
            int px = tileX + ((ni & 1) << 3) + 2 * tg;
            size_t base = ((size_t)(b * HW + py) * HW + px) * CP;
            if (co_a < F) {
                float v0 = acc[mi][ni][0] + ba; v0 = v0 > 0.f ? v0 : 0.f;
                float v1 = acc[mi][ni][1] + ba; v1 = v1 > 0.f ? v1 : 0.f;
                act_out[base + co_a] = __float2half(v0);
                act_out[base + CP + co_a] = __float2half(v1);
            }
            if (co_b < F) {
                float v2 = acc[mi][ni][2] + bb; v2 = v2 > 0.f ? v2 : 0.f;
                float v3 = acc[mi][ni][3] + bb; v3 = v3 > 0.f ? v3 : 0.f;
                act_out[base + co_b] = __float2half(v2);
                act_out[base + CP + co_b] = __float2half(v3);
            }
        }
    }
}

// ---------------------------------------------------------------------------
// Fused kp: per CTA, 64 pixels (16x4 tile). GEMM over 4 chunks of 128 wkp
// rows -> logits in smem transposed [co][pix], then softmax + apply.
// s_patch aliases the s_A region (dead after GEMM) -> smem 105216 B ->
// 2 CTAs/SM.
// ---------------------------------------------------------------------------
#define SMEM_KP2 (15360 + 30720 + 59136)   // s_px + s_A(/patch) + s_lg

__global__ __launch_bounds__(256, 2)
void kp_fused2(const __half* __restrict__ feat, const float* __restrict__ noisy,
               const __half* __restrict__ wkp, const float* __restrict__ b_kp,
               float* __restrict__ out) {
    extern __shared__ __align__(128) char smc[];
    __half* s_px = (__half*)smc;                            // [64][120]
    __half* s_A = (__half*)(smc + 15360);                   // [128][120]
    __half* s_lg = (__half*)(smc + 15360 + 30720);          // [448][66]
    float* s_patch = (float*)(smc + 15360);                 // [3][24][36], aliases s_A

    const int t = threadIdx.x;
    const int lane = t & 31, w = t >> 5;
    const int mw = w & 3, nw = w >> 2;
    const int g = lane >> 2, tg = lane & 3;
    const int tileX = (blockIdx.x % 12) * 16;
    const int tileY = (blockIdx.x / 12) * 4;
    const int b = blockIdx.z;

    {
        const __half* fb = feat + (size_t)b * HW * HW * CP;
        for (int i = t; i < 64 * 14; i += 256) {
            int pix = i / 14, j = i % 14;
            int gy = tileY + (pix >> 4), gx = tileX + (pix & 15);
            ((uint4*)&s_px[pix * PITCH])[j] =
                ((const uint4*)&fb[((size_t)gy * HW + gx) * CP])[j];
        }
    }

    uint32_t a_base[2];
#pragma unroll
    for (int mi = 0; mi < 2; mi++)
        a_base[mi] = smem_u32(&s_A[(mw * 32 + mi * 16 + (lane & 15)) * PITCH +
                                   (lane >> 4) * 8]);
    uint32_t b_base[2];
    {
        int sub = lane >> 3, pix8 = lane & 7;
#pragma unroll
        for (int j = 0; j < 2; j++) {
            int ni = 2 * j + (sub >> 1);
            int khalf = sub & 1;
            int pidx = nw * 32 + ni * 8 + pix8;
            b_base[j] = smem_u32(&s_px[pidx * PITCH + khalf * 8]);
        }
    }

#pragma unroll 1
    for (int cg = 0; cg < 4; cg++) {
        __syncthreads();   // staging done (cg=0) / prior chunk's s_A reads done
        for (int i = t; i < 128 * 14; i += 256) {
            int co = i / 14, j = i % 14;
            ((uint4*)&s_A[co * PITCH])[j] =
                ((const uint4*)&wkp[(size_t)(cg * 128 + co) * CP])[j];
        }
        __syncthreads();

        float acc[2][4][4];
#pragma unroll
        for (int mi = 0; mi < 2; mi++)
#pragma unroll
            for (int ni = 0; ni < 4; ni++)
#pragma unroll
                for (int p = 0; p < 4; p++) acc[mi][ni][p] = 0.f;

#pragma unroll
        for (int kc = 0; kc < CP; kc += 16) {
            uint32_t a[2][4];
#pragma unroll
            for (int mi = 0; mi < 2; mi++) ldm_x4(a[mi], a_base[mi] + kc * 2);
            uint32_t bf[4][2];
#pragma unroll
            for (int j = 0; j < 2; j++) {
                uint32_t r[4];
                ldm_x4(r, b_base[j] + kc * 2);
                bf[2 * j][0] = r[0]; bf[2 * j][1] = r[1];
                bf[2 * j + 1][0] = r[2]; bf[2 * j + 1][1] = r[3];
            }
#pragma unroll
            for (int mi = 0; mi < 2; mi++)
#pragma unroll
                for (int ni = 0; ni < 4; ni++)
                    mma16816(acc[mi][ni], a[mi], bf[ni]);
        }

#pragma unroll
        for (int mi = 0; mi < 2; mi++) {
            int co_a = cg * 128 + mw * 32 + mi * 16 + g;
            int co_b = co_a + 8;
            float ba = (co_a < KK) ? b_kp[co_a] : 0.f;
            float bb = (co_b < KK) ? b_kp[co_b] : 0.f;
#pragma unroll
            for (int ni = 0; ni < 4; ni++) {
                int pidx = nw * 32 + ni * 8 + 2 * tg;
                if (co_a < KK) {
                    __half2 h = __floats2half2_rn(acc[mi][ni][0] + ba,
                                                  acc[mi][ni][1] + ba);
                    *(__half2*)&s_lg[co_a * LGP + pidx] = h;
                }
                if (co_b < KK) {
                    __half2 h = __floats2half2_rn(acc[mi][ni][2] + bb,
                                                  acc[mi][ni][3] + bb);
                    *(__half2*)&s_lg[co_b * LGP + pidx] = h;
                }
            }
        }
    }
    __syncthreads();   // all s_A reads done; region reused for patch below

    // Stage noisy patch (fp32) into the dead s_A region.
    for (int i = t; i < 3 * 24 * 36; i += 256) {
        int c = i / (24 * 36);
        int rem = i - c * (24 * 36);
        int dy = rem / 36, dx = rem - dy * 36;
        int gy = tileY + dy - 10, gx = tileX + dx - 10;
        float v = 0.f;
        if ((unsigned)gy < HW && (unsigned)gx < HW)
            v = noisy[(((size_t)b * 3 + c) * HW + gy) * HW + gx];
        s_patch[(c * 24 + dy) * 36 + dx] = v;
    }
    __syncthreads();

#pragma unroll 1
    for (int it = 0; it < 8; it++) {
        int pidx = it * 8 + w;
        int py = pidx >> 4, pxl = pidx & 15;

        float L[14];
#pragma unroll
        for (int i = 0; i < 14; i++) {
            int j = i * 32 + lane;
            L[i] = (j < KK) ? __half2float(s_lg[j * LGP + pidx]) : -1e30f;
        }
        float m = -1e30f;
#pragma unroll
        for (int i = 0; i < 14; i++) m = fmaxf(m, L[i]);
#pragma unroll
        for (int o = 16; o; o >>= 1) m = fmaxf(m, __shfl_xor_sync(0xffffffffu, m, o));

        float se = 0.f, o0 = 0.f, o1 = 0.f, o2 = 0.f;
#pragma unroll
        for (int i = 0; i < 14; i++) {
            int j = i * 32 + lane;
            if (j < KK) {
                float e = __expf(L[i] - m);
                int ky = j / 21, kx = j - ky * 21;
                se += e;
                o0 += e * s_patch[(0 * 24 + py + ky) * 36 + pxl + kx];
                o1 += e * s_patch[(1 * 24 + py + ky) * 36 + pxl + kx];
                o2 += e * s_patch[(2 * 24 + py + ky) * 36 + pxl + kx];
            }
        }
#pragma unroll
        for (int o = 16; o; o >>= 1) {
            se += __shfl_xor_sync(0xffffffffu, se, o);
            o0 += __shfl_xor_sync(0xffffffffu, o0, o);
            o1 += __shfl_xor_sync(0xffffffffu, o1, o);
            o2 += __shfl_xor_sync(0xffffffffu, o2, o);
        }
        if (lane == 0) {
            float inv = 1.f / se;
            int y = tileY + py, x = tileX + pxl;
            out[(((size_t)b * 3 + 0) * HW + y) * HW + x] = o0 * inv;
            out[(((size_t)b * 3 + 1) * HW + y) * HW + x] = o1 * inv;
            out[(((size_t)b * 3 + 2) * HW + y) * HW + x] = o2 * inv;
        }
    }
}

// ---------------------------------------------------------------------------
extern "C" void kernel_launch(void* const* d_in, const int* in_sizes, int n_in,
                              void* d_out, int out_size) {
    const float* noisy = (const float*)d_in[0];
    const float* w_in  = (const float*)d_in[1];
    const float* b_in  = (const float*)d_in[2];
    const float* w_hid = (const float*)d_in[3];
    const float* b_hid = (const float*)d_in[4];
    const float* w_kp  = (const float*)d_in[5];
    const float* b_kp  = (const float*)d_in[6];
    float* out = (float*)d_out;

    __half *act0, *act1, *wt, *wkp;
    cudaGetSymbolAddress((void**)&act0, g_act0);
    cudaGetSymbolAddress((void**)&act1, g_act1);
    cudaGetSymbolAddress((void**)&wt, g_wt);
    cudaGetSymbolAddress((void**)&wkp, g_wkp);

    const int smem_hidden = 240 * PP * 2 + 2 * 112 * PP * 2;  // 103936 B
    cudaFuncSetAttribute(conv_hidden, cudaFuncAttributeMaxDynamicSharedMemorySize,
                         smem_hidden);
    cudaFuncSetAttribute(kp_fused2, cudaFuncAttributeMaxDynamicSharedMemorySize,
                         SMEM_KP2);

    wt_transform<<<(7 * 25 * 128 * CP + 255) / 256, 256>>>(w_hid);
    wkp_transform<<<(KKP * CP + 255) / 256, 256>>>(w_kp);

    conv_in<<<dim3(36, 10, 2), 256>>>(noisy, w_in, b_in, act0);

    const __half* src = act0;
    __half* dst = act1;
    for (int l = 0; l < 7; l++) {
        conv_hidden<<<dim3(288, 1, 2), 256, smem_hidden>>>(
            src, wt + (size_t)l * 25 * 128 * CP, b_hid + l * F, dst);
        __half* tmp = (__half*)src;
        src = dst;
        dst = tmp;
    }

    kp_fused2<<<dim3(576, 1, 2), 256, SMEM_KP2>>>(src, noisy, wkp, b_kp, out);
}